// round 2
// baseline (speedup 1.0000x reference)
#include <cuda_runtime.h>
#include <cuda_bf16.h>
#include <math.h>

// Problem constants
constexpr int B_  = 8;
constexpr int P_  = 196;    // 14*14 pixels
constexpr int T_  = 64;
constexpr int H_  = 768;    // HIDDEN_DIM
constexpr int MD  = 2048;   // MAP_DIM
constexpr int BP  = B_ * P_;   // 1568
constexpr int BT  = B_ * T_;   // 512

// Scratch (device globals: no allocation allowed)
__device__ float g_mlo[BP * H_];     // map_linear output (bias-preinit, red-accum)
__device__ float g_ctx[BT * MD];     // context vectors
__device__ float g_attn[BT * P_];    // fallback attn storage

// ---------------------------------------------------------------------------
// f32x2 packed helpers
// ---------------------------------------------------------------------------
__device__ __forceinline__ unsigned long long ffma2(unsigned long long a,
                                                    unsigned long long b,
                                                    unsigned long long c) {
    unsigned long long d;
    asm("fma.rn.f32x2 %0, %1, %2, %3;" : "=l"(d) : "l"(a), "l"(b), "l"(c));
    return d;
}
__device__ __forceinline__ float2 unpack2(unsigned long long v) {
    float2 f;
    asm("mov.b64 {%0, %1}, %2;" : "=f"(f.x), "=f"(f.y) : "l"(v));
    return f;
}
__device__ __forceinline__ void red_add_v4(float* p, float x, float y, float z, float w) {
    asm volatile("red.global.add.v4.f32 [%0], {%1, %2, %3, %4};"
                 :: "l"(p), "f"(x), "f"(y), "f"(z), "f"(w) : "memory");
}

// ---------------------------------------------------------------------------
// TN GEMM, split-K with red.global epilogue:
//   C[m,n] += sum_{k in chunk} A[m,k] * W[n,k]
// A: M x K row-major.  W: N x K row-major (N, K multiples of 64/32).
// BM=128, BN=64, BK=32, 128 threads, 8x8 microtile.
// A is staged into smem PRE-DUPLICATED as float2{a,a} so the inner loop is
// pure LDS.128 + FFMA2 (no splat MOVs).
// ---------------------------------------------------------------------------
constexpr int GBM = 128, GBN = 64, GBK = 32;
constexpr int ASTRIDE = GBM + 2;   // float2 units; even -> 16B-aligned rows
constexpr int BSTRIDE = GBN + 4;

__global__ void __launch_bounds__(128, 4)
gemm_tn_red(const float* __restrict__ A, const float* __restrict__ W,
            float* __restrict__ C, int M, int N, int K, int kChunk)
{
    __shared__ float2 As2[GBK][ASTRIDE];
    __shared__ float  Bs [GBK][BSTRIDE];

    const int tid = threadIdx.x;
    const int m0  = blockIdx.x * GBM;
    const int n0  = blockIdx.y * GBN;
    const int k0  = blockIdx.z * kChunk;

    const int tx = tid & 7;            // n: 0..7
    const int ty = tid >> 3;           // m: 0..15
    const int rowBase = ty * 8;
    const int colBase = tx * 8;

    unsigned long long acc[8][4];
    #pragma unroll
    for (int i = 0; i < 8; i++)
        #pragma unroll
        for (int j = 0; j < 4; j++) acc[i][j] = 0ull;

    for (int kt = k0; kt < k0 + kChunk; kt += GBK) {
        // stage A (BM x BK), duplicated
        #pragma unroll
        for (int l = 0; l < 8; l++) {                 // 1024 float4 / 128 thr
            int idx = tid + l * 128;
            int r = idx >> 3;                         // 0..127
            int c = idx & 7;                          // 0..7 (k/4)
            float4 v = make_float4(0.f, 0.f, 0.f, 0.f);
            if (m0 + r < M)
                v = *(const float4*)(A + (size_t)(m0 + r) * K + kt + 4 * c);
            As2[4 * c + 0][r] = make_float2(v.x, v.x);
            As2[4 * c + 1][r] = make_float2(v.y, v.y);
            As2[4 * c + 2][r] = make_float2(v.z, v.z);
            As2[4 * c + 3][r] = make_float2(v.w, v.w);
        }
        // stage W (BN x BK)
        #pragma unroll
        for (int l = 0; l < 4; l++) {                 // 512 float4 / 128 thr
            int idx = tid + l * 128;
            int r = idx >> 3;                         // 0..63
            int c = idx & 7;
            float4 v = *(const float4*)(W + (size_t)(n0 + r) * K + kt + 4 * c);
            Bs[4 * c + 0][r] = v.x;
            Bs[4 * c + 1][r] = v.y;
            Bs[4 * c + 2][r] = v.z;
            Bs[4 * c + 3][r] = v.w;
        }
        __syncthreads();

        #pragma unroll
        for (int k = 0; k < GBK; k++) {
            unsigned long long a[8];
            {
                const float4* ap = (const float4*)&As2[k][rowBase];
                #pragma unroll
                for (int q = 0; q < 4; q++) {
                    float4 t = ap[q];
                    a[2 * q + 0] = *(unsigned long long*)&t.x;
                    a[2 * q + 1] = *(unsigned long long*)&t.z;
                }
            }
            unsigned long long b[4];
            {
                const float4* bp = (const float4*)&Bs[k][colBase];
                float4 t0 = bp[0], t1 = bp[1];
                b[0] = *(unsigned long long*)&t0.x;
                b[1] = *(unsigned long long*)&t0.z;
                b[2] = *(unsigned long long*)&t1.x;
                b[3] = *(unsigned long long*)&t1.z;
            }
            #pragma unroll
            for (int i = 0; i < 8; i++)
                #pragma unroll
                for (int j = 0; j < 4; j++)
                    acc[i][j] = ffma2(a[i], b[j], acc[i][j]);
        }
        __syncthreads();
    }

    // split-K reduction epilogue (vector red)
    #pragma unroll
    for (int i = 0; i < 8; i++) {
        int row = m0 + rowBase + i;
        if (row >= M) continue;
        float* cp = C + (size_t)row * N + n0 + colBase;
        float2 v0 = unpack2(acc[i][0]);
        float2 v1 = unpack2(acc[i][1]);
        float2 v2 = unpack2(acc[i][2]);
        float2 v3 = unpack2(acc[i][3]);
        red_add_v4(cp + 0, v0.x, v0.y, v1.x, v1.y);
        red_add_v4(cp + 4, v2.x, v2.y, v3.x, v3.y);
    }
}

// ---------------------------------------------------------------------------
// C pre-initializers
// ---------------------------------------------------------------------------
__global__ void init_mlo_kernel(float* __restrict__ mlo, const float* __restrict__ b_map)
{
    int i = blockIdx.x * 256 + threadIdx.x;
    if (i < BP * H_) mlo[i] = b_map[i % H_];
}

__global__ void init_out_kernel(float* __restrict__ out, const float* __restrict__ b_final,
                                const float* __restrict__ hiddens)
{
    int i = blockIdx.x * 256 + threadIdx.x;
    if (i < BT * H_) out[i] = b_final[i % H_] + hiddens[i];
}

// ---------------------------------------------------------------------------
// scores + softmax (TG=8 t's per block, 512 threads)
// ---------------------------------------------------------------------------
__global__ void __launch_bounds__(512)
scores_softmax_kernel(const float* __restrict__ mlo, const float* __restrict__ hiddens,
                      const float* __restrict__ W_rect, float* __restrict__ attn_out)
{
    constexpr int TG = 8;
    __shared__ __align__(16) float s_wr[H_];
    __shared__ __align__(16) float s_hid[TG][H_];
    __shared__ float s_sc[TG][P_];

    const int b  = blockIdx.y;
    const int t0 = blockIdx.x * TG;
    const int tid = threadIdx.x;

    for (int i = tid; i < H_; i += 512) s_wr[i] = W_rect[i];
    for (int i = tid; i < TG * H_; i += 512) {
        int j = i / H_, h = i % H_;
        s_hid[j][h] = hiddens[(size_t)(b * T_ + t0 + j) * H_ + h];
    }
    __syncthreads();

    const int warp = tid >> 5;   // 0..15
    const int lane = tid & 31;

    for (int p = warp; p < P_; p += 16) {
        const float4* mrow = (const float4*)(mlo + (size_t)(b * P_ + p) * H_);
        float acc[TG] = {};
        #pragma unroll
        for (int q = lane; q < H_ / 4; q += 32) {     // 6 iterations
            float4 x = mrow[q];
            float4 w = ((const float4*)s_wr)[q];
            #pragma unroll
            for (int j = 0; j < TG; j++) {
                float4 hd = ((const float4*)s_hid[j])[q];
                acc[j] += fmaxf(x.x + hd.x, 0.f) * w.x
                        + fmaxf(x.y + hd.y, 0.f) * w.y
                        + fmaxf(x.z + hd.z, 0.f) * w.z
                        + fmaxf(x.w + hd.w, 0.f) * w.w;
            }
        }
        #pragma unroll
        for (int j = 0; j < TG; j++) {
            float v = acc[j];
            #pragma unroll
            for (int o = 16; o > 0; o >>= 1) v += __shfl_xor_sync(0xffffffffu, v, o);
            if (lane == 0) s_sc[j][p] = v;
        }
    }
    __syncthreads();

    if (warp < TG) {
        const int j = warp;
        float mx = -1e30f;
        for (int p = lane; p < P_; p += 32) mx = fmaxf(mx, s_sc[j][p]);
        #pragma unroll
        for (int o = 16; o > 0; o >>= 1) mx = fmaxf(mx, __shfl_xor_sync(0xffffffffu, mx, o));
        float sm = 0.f;
        for (int p = lane; p < P_; p += 32) {
            float e = expf(s_sc[j][p] - mx);
            s_sc[j][p] = e;
            sm += e;
        }
        #pragma unroll
        for (int o = 16; o > 0; o >>= 1) sm += __shfl_xor_sync(0xffffffffu, sm, o);
        float inv = 1.f / sm;
        float* ap = attn_out + (size_t)(b * T_ + t0 + j) * P_;
        for (int p = lane; p < P_; p += 32) ap[p] = s_sc[j][p] * inv;
    }
}

// ---------------------------------------------------------------------------
// ctx[b,t,m] = sum_p attn[b,t,p] * fm[b,p,m]
// Block = (b, 128-m tile), all 64 t. 256 threads. attn staged in DYNAMIC smem
// pre-duplicated as float2{v,v} (100 KB). p-loop unrolled x7 -> 7 LDG.128 in
// flight per thread. Inner loop: LDS.64 (broadcast) + FFMA2 only.
// ---------------------------------------------------------------------------
__global__ void __launch_bounds__(256)
ctx_kernel(const float* __restrict__ attn, const float* __restrict__ fm,
           float* __restrict__ ctx)
{
    extern __shared__ float2 s_at2[];   // [64][P_] duplicated pairs
    const int m0 = blockIdx.x * 128;
    const int b  = blockIdx.y;
    const int tid = threadIdx.x;
    const int tx = tid & 31;            // 4 m-cols each
    const int ty = tid >> 5;            // 0..7 -> 8 t each

    for (int i = tid; i < T_ * P_; i += 256) {
        float v = attn[(size_t)b * T_ * P_ + i];
        s_at2[i] = make_float2(v, v);
    }
    __syncthreads();

    unsigned long long acc[8][2];
    #pragma unroll
    for (int i = 0; i < 8; i++) { acc[i][0] = 0ull; acc[i][1] = 0ull; }

    const float* fmb = fm + (size_t)b * P_ * MD + m0 + tx * 4;

    for (int p0 = 0; p0 < P_; p0 += 7) {      // 196 = 28 * 7, exact
        unsigned long long f[7][2];
        #pragma unroll
        for (int j = 0; j < 7; j++) {
            float4 v = *(const float4*)(fmb + (size_t)(p0 + j) * MD);
            f[j][0] = *(unsigned long long*)&v.x;
            f[j][1] = *(unsigned long long*)&v.z;
        }
        #pragma unroll
        for (int j = 0; j < 7; j++) {
            #pragma unroll
            for (int i = 0; i < 8; i++) {
                unsigned long long av =
                    *(const unsigned long long*)&s_at2[(ty * 8 + i) * P_ + p0 + j];
                acc[i][0] = ffma2(av, f[j][0], acc[i][0]);
                acc[i][1] = ffma2(av, f[j][1], acc[i][1]);
            }
        }
    }

    #pragma unroll
    for (int i = 0; i < 8; i++) {
        float2 lo = unpack2(acc[i][0]);
        float2 hi = unpack2(acc[i][1]);
        float* cp = ctx + (size_t)(b * T_ + ty * 8 + i) * MD + m0 + tx * 4;
        *(float4*)cp = make_float4(lo.x, lo.y, hi.x, hi.y);
    }
}

// ---------------------------------------------------------------------------
// launch
// ---------------------------------------------------------------------------
extern "C" void kernel_launch(void* const* d_in, const int* in_sizes, int n_in,
                              void* d_out, int out_size)
{
    const float* maps    = (const float*)d_in[0];   // (BP, MD)
    const float* hiddens = (const float*)d_in[1];   // (BT, H)
    const float* W_map   = (const float*)d_in[2];   // (H, MD)
    const float* b_map   = (const float*)d_in[3];   // (H,)
    const float* W_final = (const float*)d_in[4];   // (H, MD)
    const float* b_final = (const float*)d_in[5];   // (H,)
    const float* W_rect  = (const float*)d_in[6];   // (1, H)
    // d_in[7] = b_rect : softmax-invariant, unused.

    float* out = (float*)d_out;                     // [out (BT,H) | attn (BT,P)]

    void *p_mlo_v, *p_ctx_v, *p_attn_v;
    cudaGetSymbolAddress(&p_mlo_v,  g_mlo);
    cudaGetSymbolAddress(&p_ctx_v,  g_ctx);
    cudaGetSymbolAddress(&p_attn_v, g_attn);
    float* p_mlo = (float*)p_mlo_v;
    float* p_ctx = (float*)p_ctx_v;

    float* attn = (out_size >= BT * H_ + BT * P_) ? out + (size_t)BT * H_
                                                  : (float*)p_attn_v;

    const int ctxSmem = T_ * P_ * (int)sizeof(float2);   // 100,352 bytes
    static bool s_attr_done = false;
    if (!s_attr_done) {
        cudaFuncSetAttribute(ctx_kernel,
                             cudaFuncAttributeMaxDynamicSharedMemorySize, ctxSmem);
        s_attr_done = true;
    }

    // 1. mlo = b_map (broadcast)
    init_mlo_kernel<<<(BP * H_ + 255) / 256, 256>>>(p_mlo, b_map);

    // 2. mlo += fm @ W_map^T    (split-K=2)
    gemm_tn_red<<<dim3((BP + GBM - 1) / GBM, H_ / GBN, 2), 128>>>(
        maps, W_map, p_mlo, BP, H_, MD, MD / 2);

    // 3. scores + softmax -> attn
    scores_softmax_kernel<<<dim3(T_ / 8, B_), 512>>>(p_mlo, hiddens, W_rect, attn);

    // 4. ctx = attn @ fm (per batch)
    ctx_kernel<<<dim3(MD / 128, B_), 256, ctxSmem>>>(attn, maps, p_ctx);

    // 5. out = b_final + hiddens
    init_out_kernel<<<(BT * H_ + 255) / 256, 256>>>(out, b_final, hiddens);

    // 6. out += ctx @ W_final^T  (split-K=4)
    gemm_tn_red<<<dim3(BT / GBM, H_ / GBN, 4), 128>>>(
        p_ctx, W_final, out, BT, H_, MD, MD / 4);
}

// round 6
// speedup vs baseline: 1.6393x; 1.6393x over previous
#include <cuda_runtime.h>
#include <cuda_bf16.h>
#include <math.h>
#include <stdint.h>

// Problem constants
constexpr int B_  = 8;
constexpr int P_  = 196;
constexpr int T_  = 64;
constexpr int H_  = 768;
constexpr int MD  = 2048;
constexpr int BP  = B_ * P_;   // 1568
constexpr int BT  = B_ * T_;   // 512
constexpr int NCH = MD / 64;   // 32 K-chunks of 64

// ---------------------------------------------------------------------------
// Scratch (device globals; no allocation allowed)
// ---------------------------------------------------------------------------
__device__ float g_mlo[BP * H_];
__device__ float g_attn_fb[BT * P_];
__device__ __align__(16) __nv_bfloat16 g_a_hi[BP * MD],  g_a_lo[BP * MD];
__device__ __align__(16) __nv_bfloat16 g_wm_hi[H_ * MD], g_wm_lo[H_ * MD];
__device__ __align__(16) __nv_bfloat16 g_wf_hi[H_ * MD], g_wf_lo[H_ * MD];
__device__ __align__(16) __nv_bfloat16 g_cx_hi[BT * MD], g_cx_lo[BT * MD];

// ---------------------------------------------------------------------------
// PTX helpers (base-ISA only: ldmatrix / mma.sync / cp.async)
// ---------------------------------------------------------------------------
__device__ __forceinline__ uint32_t smem_u32(const void* p) {
    uint32_t a;
    asm("{ .reg .u64 t; cvta.to.shared.u64 t, %1; cvt.u32.u64 %0, t; }"
        : "=r"(a) : "l"(p));
    return a;
}
__device__ __forceinline__ uint32_t swz(uint32_t o) { return o ^ ((o >> 3) & 0x70); }

__device__ __forceinline__ void cp16(uint32_t dst, const void* src, int srcsz) {
    asm volatile("cp.async.cg.shared.global [%0], [%1], 16, %2;"
                 :: "r"(dst), "l"(src), "r"(srcsz));
}
__device__ __forceinline__ void ldsm_x4(uint32_t& r0, uint32_t& r1, uint32_t& r2,
                                        uint32_t& r3, uint32_t a) {
    asm volatile("ldmatrix.sync.aligned.m8n8.x4.shared.b16 {%0,%1,%2,%3}, [%4];"
                 : "=r"(r0), "=r"(r1), "=r"(r2), "=r"(r3) : "r"(a));
}
// B operand: W stored [n][k] row-major == column-major B(k,n) -> NO trans.
__device__ __forceinline__ void ldsm_x2(uint32_t& r0, uint32_t& r1, uint32_t a) {
    asm volatile("ldmatrix.sync.aligned.m8n8.x2.shared.b16 {%0,%1}, [%2];"
                 : "=r"(r0), "=r"(r1) : "r"(a));
}
__device__ __forceinline__ void mma16816(float c[4], const uint32_t a[4],
                                         const uint32_t b[2]) {
    asm volatile("mma.sync.aligned.m16n8k16.row.col.f32.bf16.bf16.f32 "
                 "{%0,%1,%2,%3}, {%4,%5,%6,%7}, {%8,%9}, {%0,%1,%2,%3};"
                 : "+f"(c[0]), "+f"(c[1]), "+f"(c[2]), "+f"(c[3])
                 : "r"(a[0]), "r"(a[1]), "r"(a[2]), "r"(a[3]),
                   "r"(b[0]), "r"(b[1]));
}

// f32x2 helpers (ctx kernel)
__device__ __forceinline__ unsigned long long ffma2(unsigned long long a,
                                                    unsigned long long b,
                                                    unsigned long long c) {
    unsigned long long d;
    asm("fma.rn.f32x2 %0, %1, %2, %3;" : "=l"(d) : "l"(a), "l"(b), "l"(c));
    return d;
}
__device__ __forceinline__ float2 unpack2(unsigned long long v) {
    float2 f;
    asm("mov.b64 {%0, %1}, %2;" : "=f"(f.x), "=f"(f.y) : "l"(v));
    return f;
}

// ---------------------------------------------------------------------------
// fp32 -> (bf16 hi, bf16 lo) split conversion
// ---------------------------------------------------------------------------
__global__ void convert_split(const float4* __restrict__ src,
                              uint2* __restrict__ hi, uint2* __restrict__ lo, int n4)
{
    int i = blockIdx.x * 256 + threadIdx.x;
    if (i >= n4) return;
    float4 v = src[i];
    __nv_bfloat16 h0 = __float2bfloat16(v.x), h1 = __float2bfloat16(v.y);
    __nv_bfloat16 h2 = __float2bfloat16(v.z), h3 = __float2bfloat16(v.w);
    __nv_bfloat16 l0 = __float2bfloat16(v.x - __bfloat162float(h0));
    __nv_bfloat16 l1 = __float2bfloat16(v.y - __bfloat162float(h1));
    __nv_bfloat16 l2 = __float2bfloat16(v.z - __bfloat162float(h2));
    __nv_bfloat16 l3 = __float2bfloat16(v.w - __bfloat162float(h3));
    __nv_bfloat162 ha = __halves2bfloat162(h0, h1), hb = __halves2bfloat162(h2, h3);
    __nv_bfloat162 la = __halves2bfloat162(l0, l1), lb = __halves2bfloat162(l2, l3);
    uint2 uh, ul;
    uh.x = *(uint32_t*)&ha; uh.y = *(uint32_t*)&hb;
    ul.x = *(uint32_t*)&la; ul.y = *(uint32_t*)&lb;
    hi[i] = uh;
    lo[i] = ul;
}

// ---------------------------------------------------------------------------
// mma.sync split-bf16 TN GEMM:
//   C[m,n] = sum_k A[m,k]*W[n,k] + bias[n] (+ addin[m,n])
// A ~ Ahi+Alo, W ~ Whi+Wlo, 3 product terms (hh, hl, lh).
// 256 threads = 8 warps (2 m x 4 n). BM = MT*32, BN = 64, BK = 64 (bf16).
// SMEM: SW128-swizzled 128B rows; cp.async double-buffered.
// ---------------------------------------------------------------------------
template<int MT>
__global__ void __launch_bounds__(256, 1)
gemm_mma_bf16x3(const __nv_bfloat16* __restrict__ aHi, const __nv_bfloat16* __restrict__ aLo,
                const __nv_bfloat16* __restrict__ wHi, const __nv_bfloat16* __restrict__ wLo,
                const float* __restrict__ bias, const float* __restrict__ addin,
                float* __restrict__ C, int M)
{
    constexpr int BM  = MT * 32;
    constexpr int A_B = BM * 128;       // bytes per A tile (BM rows x 128B)
    constexpr int W_B = 64 * 128;
    constexpr int BUF = 2 * A_B + 2 * W_B;

    extern __shared__ __align__(1024) char smem[];
    const uint32_t sb = smem_u32(smem);
    const int tid = threadIdx.x, lane = tid & 31, wid = tid >> 5;
    const int wm = wid >> 2, wn = wid & 3;
    const int m0 = blockIdx.x * BM, n0 = blockIdx.y * 64;

    auto stage = [&](int c) {
        const uint32_t base = sb + (c & 1) * BUF;
        const int kt = c * 64;
        #pragma unroll
        for (int l = 0; l < MT; l++) {
            int idx = tid + l * 256;
            int r = idx >> 3, cc = idx & 7;
            uint32_t so = swz((uint32_t)(r * 128 + cc * 16));
            int row = m0 + r;
            int sz  = (row < M) ? 16 : 0;
            size_t off = (size_t)(sz ? row : 0) * MD + kt + cc * 8;
            cp16(base + so,       aHi + off, sz);
            cp16(base + A_B + so, aLo + off, sz);
        }
        #pragma unroll
        for (int l = 0; l < 2; l++) {
            int idx = tid + l * 256;
            int r = idx >> 3, cc = idx & 7;
            uint32_t so = swz((uint32_t)(r * 128 + cc * 16));
            size_t off = (size_t)(n0 + r) * MD + kt + cc * 8;
            cp16(base + 2 * A_B + so,       wHi + off, 16);
            cp16(base + 2 * A_B + W_B + so, wLo + off, 16);
        }
        asm volatile("cp.async.commit_group;" ::: "memory");
    };

    float acc[MT][2][4];
    #pragma unroll
    for (int i = 0; i < MT; i++)
        #pragma unroll
        for (int j = 0; j < 2; j++)
            #pragma unroll
            for (int q = 0; q < 4; q++) acc[i][j][q] = 0.f;

    stage(0);
    stage(1);

    for (int c = 0; c < NCH; c++) {
        asm volatile("cp.async.wait_group 1;" ::: "memory");
        __syncthreads();
        const uint32_t base = sb + (c & 1) * BUF;
        const uint32_t Ah = base, Al = base + A_B;
        const uint32_t Wh = base + 2 * A_B, Wl = Wh + W_B;

        #pragma unroll
        for (int ks = 0; ks < 4; ks++) {
            uint32_t bh[2][2], bl[2][2];
            #pragma unroll
            for (int nt = 0; nt < 2; nt++) {
                uint32_t so = swz((uint32_t)((wn * 16 + nt * 8 + (lane & 7)) * 128
                                             + ks * 32 + ((lane >> 3) & 1) * 16));
                ldsm_x2(bh[nt][0], bh[nt][1], Wh + so);
                ldsm_x2(bl[nt][0], bl[nt][1], Wl + so);
            }
            #pragma unroll
            for (int mt = 0; mt < MT; mt++) {
                uint32_t so = swz((uint32_t)((wm * (MT * 16) + mt * 16 + (lane & 15)) * 128
                                             + ks * 32 + (lane >> 4) * 16));
                uint32_t ah[4], al[4];
                ldsm_x4(ah[0], ah[1], ah[2], ah[3], Ah + so);
                ldsm_x4(al[0], al[1], al[2], al[3], Al + so);
                #pragma unroll
                for (int nt = 0; nt < 2; nt++) {
                    mma16816(acc[mt][nt], ah, bh[nt]);
                    mma16816(acc[mt][nt], ah, bl[nt]);
                    mma16816(acc[mt][nt], al, bh[nt]);
                }
            }
        }
        __syncthreads();
        if (c + 2 < NCH) stage(c + 2);
        else asm volatile("cp.async.commit_group;" ::: "memory");
    }
    asm volatile("cp.async.wait_group 0;" ::: "memory");

    // epilogue: registers -> global, + bias (+ addin)
    #pragma unroll
    for (int mt = 0; mt < MT; mt++) {
        #pragma unroll
        for (int half = 0; half < 2; half++) {
            int row = m0 + wm * (MT * 16) + mt * 16 + half * 8 + (lane >> 2);
            if (row >= M) continue;
            #pragma unroll
            for (int nt = 0; nt < 2; nt++) {
                int col = n0 + wn * 16 + nt * 8 + (lane & 3) * 2;
                float2 v;
                v.x = acc[mt][nt][half * 2 + 0];
                v.y = acc[mt][nt][half * 2 + 1];
                float2 bv = *(const float2*)(bias + col);
                v.x += bv.x; v.y += bv.y;
                if (addin) {
                    float2 h = *(const float2*)(addin + (size_t)row * H_ + col);
                    v.x += h.x; v.y += h.y;
                }
                *(float2*)(C + (size_t)row * H_ + col) = v;
            }
        }
    }
}

// ---------------------------------------------------------------------------
// scores + softmax (TG=8 t's per block, 512 threads)
// ---------------------------------------------------------------------------
__global__ void __launch_bounds__(512)
scores_softmax_kernel(const float* __restrict__ mlo, const float* __restrict__ hiddens,
                      const float* __restrict__ W_rect, float* __restrict__ attn_out)
{
    constexpr int TG = 8;
    __shared__ __align__(16) float s_wr[H_];
    __shared__ __align__(16) float s_hid[TG][H_];
    __shared__ float s_sc[TG][P_];

    const int b  = blockIdx.y;
    const int t0 = blockIdx.x * TG;
    const int tid = threadIdx.x;

    for (int i = tid; i < H_; i += 512) s_wr[i] = W_rect[i];
    for (int i = tid; i < TG * H_; i += 512) {
        int j = i / H_, h = i % H_;
        s_hid[j][h] = hiddens[(size_t)(b * T_ + t0 + j) * H_ + h];
    }
    __syncthreads();

    const int warp = tid >> 5;
    const int lane = tid & 31;

    for (int p = warp; p < P_; p += 16) {
        const float4* mrow = (const float4*)(mlo + (size_t)(b * P_ + p) * H_);
        float acc[TG] = {};
        #pragma unroll
        for (int q = lane; q < H_ / 4; q += 32) {
            float4 x = mrow[q];
            float4 w = ((const float4*)s_wr)[q];
            #pragma unroll
            for (int j = 0; j < TG; j++) {
                float4 hd = ((const float4*)s_hid[j])[q];
                acc[j] += fmaxf(x.x + hd.x, 0.f) * w.x
                        + fmaxf(x.y + hd.y, 0.f) * w.y
                        + fmaxf(x.z + hd.z, 0.f) * w.z
                        + fmaxf(x.w + hd.w, 0.f) * w.w;
            }
        }
        #pragma unroll
        for (int j = 0; j < TG; j++) {
            float v = acc[j];
            #pragma unroll
            for (int o = 16; o > 0; o >>= 1) v += __shfl_xor_sync(0xffffffffu, v, o);
            if (lane == 0) s_sc[j][p] = v;
        }
    }
    __syncthreads();

    if (warp < TG) {
        const int j = warp;
        float mx = -1e30f;
        for (int p = lane; p < P_; p += 32) mx = fmaxf(mx, s_sc[j][p]);
        #pragma unroll
        for (int o = 16; o > 0; o >>= 1) mx = fmaxf(mx, __shfl_xor_sync(0xffffffffu, mx, o));
        float sm = 0.f;
        for (int p = lane; p < P_; p += 32) {
            float e = expf(s_sc[j][p] - mx);
            s_sc[j][p] = e;
            sm += e;
        }
        #pragma unroll
        for (int o = 16; o > 0; o >>= 1) sm += __shfl_xor_sync(0xffffffffu, sm, o);
        float inv = 1.f / sm;
        float* ap = attn_out + (size_t)(b * T_ + t0 + j) * P_;
        for (int p = lane; p < P_; p += 32) ap[p] = s_sc[j][p] * inv;
    }
}

// ---------------------------------------------------------------------------
// ctx[b,t,m] = sum_p attn[b,t,p] * fm[b,p,m]; writes bf16 hi/lo split.
// 512 threads; 16 warps x 4 t's; 7-deep LDG.128 pipeline.
// ---------------------------------------------------------------------------
__global__ void __launch_bounds__(512)
ctx_kernel(const float* __restrict__ attn, const float* __restrict__ fm,
           __nv_bfloat16* __restrict__ cxh, __nv_bfloat16* __restrict__ cxl)
{
    extern __shared__ float2 s_at2[];     // [64][P_] duplicated pairs (100 KB)
    const int m0 = blockIdx.x * 128;
    const int b  = blockIdx.y;
    const int tid = threadIdx.x;
    const int tx = tid & 31;
    const int ty = tid >> 5;

    for (int i = tid; i < T_ * P_; i += 512) {
        float v = attn[(size_t)b * T_ * P_ + i];
        s_at2[i] = make_float2(v, v);
    }
    __syncthreads();

    unsigned long long acc[4][2] = {};
    const float* fmb = fm + (size_t)b * P_ * MD + m0 + tx * 4;

    for (int p0 = 0; p0 < P_; p0 += 7) {          // 196 = 28 * 7
        unsigned long long f[7][2];
        #pragma unroll
        for (int j = 0; j < 7; j++) {
            float4 v = *(const float4*)(fmb + (size_t)(p0 + j) * MD);
            f[j][0] = *(unsigned long long*)&v.x;
            f[j][1] = *(unsigned long long*)&v.z;
        }
        #pragma unroll
        for (int j = 0; j < 7; j++) {
            #pragma unroll
            for (int i = 0; i < 4; i++) {
                unsigned long long av =
                    *(const unsigned long long*)&s_at2[(ty * 4 + i) * P_ + p0 + j];
                acc[i][0] = ffma2(av, f[j][0], acc[i][0]);
                acc[i][1] = ffma2(av, f[j][1], acc[i][1]);
            }
        }
    }

    #pragma unroll
    for (int i = 0; i < 4; i++) {
        float2 c01 = unpack2(acc[i][0]);
        float2 c23 = unpack2(acc[i][1]);
        float v0 = c01.x, v1 = c01.y, v2 = c23.x, v3 = c23.y;
        __nv_bfloat16 h0 = __float2bfloat16(v0), h1 = __float2bfloat16(v1);
        __nv_bfloat16 h2 = __float2bfloat16(v2), h3 = __float2bfloat16(v3);
        __nv_bfloat16 l0 = __float2bfloat16(v0 - __bfloat162float(h0));
        __nv_bfloat16 l1 = __float2bfloat16(v1 - __bfloat162float(h1));
        __nv_bfloat16 l2 = __float2bfloat16(v2 - __bfloat162float(h2));
        __nv_bfloat16 l3 = __float2bfloat16(v3 - __bfloat162float(h3));
        size_t off = (size_t)(b * T_ + ty * 4 + i) * MD + m0 + tx * 4;
        __nv_bfloat162 ha = __halves2bfloat162(h0, h1), hb = __halves2bfloat162(h2, h3);
        __nv_bfloat162 la = __halves2bfloat162(l0, l1), lb = __halves2bfloat162(l2, l3);
        uint2 uh, ul;
        uh.x = *(uint32_t*)&ha; uh.y = *(uint32_t*)&hb;
        ul.x = *(uint32_t*)&la; ul.y = *(uint32_t*)&lb;
        *(uint2*)(cxh + off) = uh;
        *(uint2*)(cxl + off) = ul;
    }
}

// ---------------------------------------------------------------------------
// launch
// ---------------------------------------------------------------------------
extern "C" void kernel_launch(void* const* d_in, const int* in_sizes, int n_in,
                              void* d_out, int out_size)
{
    const float* maps    = (const float*)d_in[0];
    const float* hiddens = (const float*)d_in[1];
    const float* W_map   = (const float*)d_in[2];
    const float* b_map   = (const float*)d_in[3];
    const float* W_final = (const float*)d_in[4];
    const float* b_final = (const float*)d_in[5];
    const float* W_rect  = (const float*)d_in[6];
    // d_in[7] = b_rect : softmax-invariant, unused.

    float* out = (float*)d_out;       // [out (BT,H) | attn (BT,P)]

    void *v0, *v1, *v2, *v3, *v4, *v5, *v6, *v7, *v8, *v9;
    cudaGetSymbolAddress(&v0, g_mlo);
    cudaGetSymbolAddress(&v1, g_attn_fb);
    cudaGetSymbolAddress(&v2, g_a_hi);  cudaGetSymbolAddress(&v3, g_a_lo);
    cudaGetSymbolAddress(&v4, g_wm_hi); cudaGetSymbolAddress(&v5, g_wm_lo);
    cudaGetSymbolAddress(&v6, g_wf_hi); cudaGetSymbolAddress(&v7, g_wf_lo);
    cudaGetSymbolAddress(&v8, g_cx_hi); cudaGetSymbolAddress(&v9, g_cx_lo);
    float* p_mlo = (float*)v0;
    __nv_bfloat16 *aHi = (__nv_bfloat16*)v2, *aLo = (__nv_bfloat16*)v3;
    __nv_bfloat16 *wmHi = (__nv_bfloat16*)v4, *wmLo = (__nv_bfloat16*)v5;
    __nv_bfloat16 *wfHi = (__nv_bfloat16*)v6, *wfLo = (__nv_bfloat16*)v7;
    __nv_bfloat16 *cxHi = (__nv_bfloat16*)v8, *cxLo = (__nv_bfloat16*)v9;

    float* attn = (out_size >= BT * H_ + BT * P_) ? out + (size_t)BT * H_
                                                  : (float*)v1;

    constexpr int SMEM_G1 = 2 * (2 * 128 * 128 + 2 * 64 * 128);   // 98304
    constexpr int SMEM_G4 = 2 * (2 * 64 * 128 + 2 * 64 * 128);    // 65536
    cudaFuncSetAttribute(gemm_mma_bf16x3<4>,
                         cudaFuncAttributeMaxDynamicSharedMemorySize, SMEM_G1);
    cudaFuncSetAttribute(gemm_mma_bf16x3<2>,
                         cudaFuncAttributeMaxDynamicSharedMemorySize, SMEM_G4);
    const int ctxSmem = T_ * P_ * (int)sizeof(float2);
    cudaFuncSetAttribute(ctx_kernel,
                         cudaFuncAttributeMaxDynamicSharedMemorySize, ctxSmem);

    // 1. split-convert inputs to bf16 hi/lo
    convert_split<<<(BP * MD / 4 + 255) / 256, 256>>>(
        (const float4*)maps, (uint2*)aHi, (uint2*)aLo, BP * MD / 4);
    convert_split<<<(H_ * MD / 4 + 255) / 256, 256>>>(
        (const float4*)W_map, (uint2*)wmHi, (uint2*)wmLo, H_ * MD / 4);
    convert_split<<<(H_ * MD / 4 + 255) / 256, 256>>>(
        (const float4*)W_final, (uint2*)wfHi, (uint2*)wfLo, H_ * MD / 4);

    // 2. mlo = maps @ W_map^T + b_map   (13 x 12 blocks)
    gemm_mma_bf16x3<4><<<dim3((BP + 127) / 128, H_ / 64), 256, SMEM_G1>>>(
        aHi, aLo, wmHi, wmLo, b_map, nullptr, p_mlo, BP);

    // 3. scores + softmax -> attn
    scores_softmax_kernel<<<dim3(T_ / 8, B_), 512>>>(p_mlo, hiddens, W_rect, attn);

    // 4. ctx = attn @ fm  (writes bf16 hi/lo split directly)
    ctx_kernel<<<dim3(MD / 128, B_), 512, ctxSmem>>>(attn, maps, cxHi, cxLo);

    // 5. out = ctx @ W_final^T + b_final + hiddens   (8 x 12 blocks)
    gemm_mma_bf16x3<2><<<dim3(BT / 64, H_ / 64), 256, SMEM_G4>>>(
        cxHi, cxLo, wfHi, wfLo, b_final, hiddens, out, BT);
}

// round 7
// speedup vs baseline: 1.8741x; 1.1432x over previous
#include <cuda_runtime.h>
#include <cuda_bf16.h>
#include <math.h>
#include <stdint.h>

// Problem constants
constexpr int B_  = 8;
constexpr int P_  = 196;
constexpr int T_  = 64;
constexpr int H_  = 768;
constexpr int MD  = 2048;
constexpr int BP  = B_ * P_;   // 1568
constexpr int BT  = B_ * T_;   // 512
constexpr int NCH = MD / 64;   // 32 K-chunks of 64

// ---------------------------------------------------------------------------
// Scratch (device globals; no allocation allowed)
// ---------------------------------------------------------------------------
__device__ float g_mlo[BP * H_];
__device__ float g_attn_fb[BT * P_];
__device__ __align__(16) __nv_bfloat16 g_a_hi[BP * MD],  g_a_lo[BP * MD];
__device__ __align__(16) __nv_bfloat16 g_wm_hi[H_ * MD], g_wm_lo[H_ * MD];
__device__ __align__(16) __nv_bfloat16 g_wf_hi[H_ * MD], g_wf_lo[H_ * MD];
__device__ __align__(16) __nv_bfloat16 g_cx_hi[BT * MD], g_cx_lo[BT * MD];

// ---------------------------------------------------------------------------
// PTX helpers (base-ISA only: ldmatrix / mma.sync / cp.async)
// ---------------------------------------------------------------------------
__device__ __forceinline__ uint32_t smem_u32(const void* p) {
    uint32_t a;
    asm("{ .reg .u64 t; cvta.to.shared.u64 t, %1; cvt.u32.u64 %0, t; }"
        : "=r"(a) : "l"(p));
    return a;
}
__device__ __forceinline__ uint32_t swz(uint32_t o) { return o ^ ((o >> 3) & 0x70); }

__device__ __forceinline__ void cp16(uint32_t dst, const void* src, int srcsz) {
    asm volatile("cp.async.cg.shared.global [%0], [%1], 16, %2;"
                 :: "r"(dst), "l"(src), "r"(srcsz));
}
__device__ __forceinline__ void ldsm_x4(uint32_t& r0, uint32_t& r1, uint32_t& r2,
                                        uint32_t& r3, uint32_t a) {
    asm volatile("ldmatrix.sync.aligned.m8n8.x4.shared.b16 {%0,%1,%2,%3}, [%4];"
                 : "=r"(r0), "=r"(r1), "=r"(r2), "=r"(r3) : "r"(a));
}
// B operand: W stored [n][k] row-major == column-major B(k,n) -> NO trans.
__device__ __forceinline__ void ldsm_x2(uint32_t& r0, uint32_t& r1, uint32_t a) {
    asm volatile("ldmatrix.sync.aligned.m8n8.x2.shared.b16 {%0,%1}, [%2];"
                 : "=r"(r0), "=r"(r1) : "r"(a));
}
__device__ __forceinline__ void mma16816(float c[4], const uint32_t a[4],
                                         const uint32_t b[2]) {
    asm volatile("mma.sync.aligned.m16n8k16.row.col.f32.bf16.bf16.f32 "
                 "{%0,%1,%2,%3}, {%4,%5,%6,%7}, {%8,%9}, {%0,%1,%2,%3};"
                 : "+f"(c[0]), "+f"(c[1]), "+f"(c[2]), "+f"(c[3])
                 : "r"(a[0]), "r"(a[1]), "r"(a[2]), "r"(a[3]),
                   "r"(b[0]), "r"(b[1]));
}

// f32x2 helpers (ctx kernel)
__device__ __forceinline__ unsigned long long ffma2(unsigned long long a,
                                                    unsigned long long b,
                                                    unsigned long long c) {
    unsigned long long d;
    asm("fma.rn.f32x2 %0, %1, %2, %3;" : "=l"(d) : "l"(a), "l"(b), "l"(c));
    return d;
}
__device__ __forceinline__ float2 unpack2(unsigned long long v) {
    float2 f;
    asm("mov.b64 {%0, %1}, %2;" : "=f"(f.x), "=f"(f.y) : "l"(v));
    return f;
}

// ---------------------------------------------------------------------------
// Fused fp32 -> (bf16 hi, bf16 lo) split conversion for all three tensors.
// Grid-stride over the concatenated element range.
// ---------------------------------------------------------------------------
constexpr int N4_A = BP * MD / 4;     // 802816
constexpr int N4_W = H_ * MD / 4;     // 393216
constexpr int N4_TOT = N4_A + 2 * N4_W;

__global__ void convert_split_all(const float4* __restrict__ sA,
                                  const float4* __restrict__ sWm,
                                  const float4* __restrict__ sWf,
                                  uint2* __restrict__ aH, uint2* __restrict__ aL,
                                  uint2* __restrict__ wmH, uint2* __restrict__ wmL,
                                  uint2* __restrict__ wfH, uint2* __restrict__ wfL)
{
    for (int i = blockIdx.x * 256 + threadIdx.x; i < N4_TOT; i += gridDim.x * 256) {
        const float4* src;
        uint2 *hi, *lo;
        int j;
        if (i < N4_A)              { src = sA;  hi = aH;  lo = aL;  j = i; }
        else if (i < N4_A + N4_W)  { src = sWm; hi = wmH; lo = wmL; j = i - N4_A; }
        else                       { src = sWf; hi = wfH; lo = wfL; j = i - N4_A - N4_W; }
        float4 v = src[j];
        __nv_bfloat16 h0 = __float2bfloat16(v.x), h1 = __float2bfloat16(v.y);
        __nv_bfloat16 h2 = __float2bfloat16(v.z), h3 = __float2bfloat16(v.w);
        __nv_bfloat16 l0 = __float2bfloat16(v.x - __bfloat162float(h0));
        __nv_bfloat16 l1 = __float2bfloat16(v.y - __bfloat162float(h1));
        __nv_bfloat16 l2 = __float2bfloat16(v.z - __bfloat162float(h2));
        __nv_bfloat16 l3 = __float2bfloat16(v.w - __bfloat162float(h3));
        __nv_bfloat162 ha = __halves2bfloat162(h0, h1), hb = __halves2bfloat162(h2, h3);
        __nv_bfloat162 la = __halves2bfloat162(l0, l1), lb = __halves2bfloat162(l2, l3);
        uint2 uh, ul;
        uh.x = *(uint32_t*)&ha; uh.y = *(uint32_t*)&hb;
        ul.x = *(uint32_t*)&la; ul.y = *(uint32_t*)&lb;
        hi[j] = uh;
        lo[j] = ul;
    }
}

// ---------------------------------------------------------------------------
// mma.sync split-bf16 TN GEMM:
//   C[m,n] = sum_k A[m,k]*W[n,k] + bias[n] (+ addin[m,n])
// A ~ Ahi+Alo, W ~ Whi+Wlo, 3 product terms (hh, hl, lh).
// 256 threads = 8 warps arranged NWM x (8/NWM). BM = NWM*MT*16, BN = (8/NWM)*16.
// SMEM: SW128-swizzled 128B rows; cp.async double-buffered. 2+ CTAs/SM.
// ---------------------------------------------------------------------------
template<int MT, int NWM>
__global__ void __launch_bounds__(256, 2)
gemm_mma_bf16x3(const __nv_bfloat16* __restrict__ aHi, const __nv_bfloat16* __restrict__ aLo,
                const __nv_bfloat16* __restrict__ wHi, const __nv_bfloat16* __restrict__ wLo,
                const float* __restrict__ bias, const float* __restrict__ addin,
                float* __restrict__ C, int M)
{
    constexpr int NWN = 8 / NWM;
    constexpr int BM  = NWM * MT * 16;
    constexpr int BN  = NWN * 16;
    constexpr int A_B = BM * 128;       // bytes per A tile (BM rows x 128B)
    constexpr int W_B = BN * 128;
    constexpr int BUF = 2 * A_B + 2 * W_B;

    extern __shared__ __align__(1024) char smem[];
    const uint32_t sb = smem_u32(smem);
    const int tid = threadIdx.x, lane = tid & 31, wid = tid >> 5;
    const int wm = wid / NWN, wn = wid % NWN;
    const int m0 = blockIdx.x * BM, n0 = blockIdx.y * BN;

    auto stage = [&](int c) {
        const uint32_t base = sb + (c & 1) * BUF;
        const int kt = c * 64;
        #pragma unroll
        for (int l = 0; l < BM * 8 / 256; l++) {
            int idx = tid + l * 256;
            int r = idx >> 3, cc = idx & 7;
            uint32_t so = swz((uint32_t)(r * 128 + cc * 16));
            int row = m0 + r;
            int sz  = (row < M) ? 16 : 0;
            size_t off = (size_t)(sz ? row : 0) * MD + kt + cc * 8;
            cp16(base + so,       aHi + off, sz);
            cp16(base + A_B + so, aLo + off, sz);
        }
        #pragma unroll
        for (int l = 0; l < BN * 8 / 256; l++) {
            int idx = tid + l * 256;
            int r = idx >> 3, cc = idx & 7;
            uint32_t so = swz((uint32_t)(r * 128 + cc * 16));
            size_t off = (size_t)(n0 + r) * MD + kt + cc * 8;
            cp16(base + 2 * A_B + so,       wHi + off, 16);
            cp16(base + 2 * A_B + W_B + so, wLo + off, 16);
        }
        asm volatile("cp.async.commit_group;" ::: "memory");
    };

    float acc[MT][2][4];
    #pragma unroll
    for (int i = 0; i < MT; i++)
        #pragma unroll
        for (int j = 0; j < 2; j++)
            #pragma unroll
            for (int q = 0; q < 4; q++) acc[i][j][q] = 0.f;

    stage(0);
    stage(1);

    for (int c = 0; c < NCH; c++) {
        asm volatile("cp.async.wait_group 1;" ::: "memory");
        __syncthreads();
        const uint32_t base = sb + (c & 1) * BUF;
        const uint32_t Ah = base, Al = base + A_B;
        const uint32_t Wh = base + 2 * A_B, Wl = Wh + W_B;

        #pragma unroll
        for (int ks = 0; ks < 4; ks++) {
            uint32_t bh[2][2], bl[2][2];
            #pragma unroll
            for (int nt = 0; nt < 2; nt++) {
                uint32_t so = swz((uint32_t)((wn * 16 + nt * 8 + (lane & 7)) * 128
                                             + ks * 32 + ((lane >> 3) & 1) * 16));
                ldsm_x2(bh[nt][0], bh[nt][1], Wh + so);
                ldsm_x2(bl[nt][0], bl[nt][1], Wl + so);
            }
            #pragma unroll
            for (int mt = 0; mt < MT; mt++) {
                uint32_t so = swz((uint32_t)((wm * (MT * 16) + mt * 16 + (lane & 15)) * 128
                                             + ks * 32 + (lane >> 4) * 16));
                uint32_t ah[4], al[4];
                ldsm_x4(ah[0], ah[1], ah[2], ah[3], Ah + so);
                ldsm_x4(al[0], al[1], al[2], al[3], Al + so);
                #pragma unroll
                for (int nt = 0; nt < 2; nt++) {
                    mma16816(acc[mt][nt], ah, bh[nt]);
                    mma16816(acc[mt][nt], ah, bl[nt]);
                    mma16816(acc[mt][nt], al, bh[nt]);
                }
            }
        }
        __syncthreads();
        if (c + 2 < NCH) stage(c + 2);
        else asm volatile("cp.async.commit_group;" ::: "memory");
    }
    asm volatile("cp.async.wait_group 0;" ::: "memory");

    // epilogue: registers -> global, + bias (+ addin)
    #pragma unroll
    for (int mt = 0; mt < MT; mt++) {
        #pragma unroll
        for (int half = 0; half < 2; half++) {
            int row = m0 + wm * (MT * 16) + mt * 16 + half * 8 + (lane >> 2);
            if (row >= M) continue;
            #pragma unroll
            for (int nt = 0; nt < 2; nt++) {
                int col = n0 + wn * 16 + nt * 8 + (lane & 3) * 2;
                float2 v;
                v.x = acc[mt][nt][half * 2 + 0];
                v.y = acc[mt][nt][half * 2 + 1];
                float2 bv = *(const float2*)(bias + col);
                v.x += bv.x; v.y += bv.y;
                if (addin) {
                    float2 h = *(const float2*)(addin + (size_t)row * H_ + col);
                    v.x += h.x; v.y += h.y;
                }
                *(float2*)(C + (size_t)row * H_ + col) = v;
            }
        }
    }
}

// ---------------------------------------------------------------------------
// scores + softmax (TG=8 t's per block, 512 threads)
// ---------------------------------------------------------------------------
__global__ void __launch_bounds__(512)
scores_softmax_kernel(const float* __restrict__ mlo, const float* __restrict__ hiddens,
                      const float* __restrict__ W_rect, float* __restrict__ attn_out)
{
    constexpr int TG = 8;
    __shared__ __align__(16) float s_wr[H_];
    __shared__ __align__(16) float s_hid[TG][H_];
    __shared__ float s_sc[TG][P_];

    const int b  = blockIdx.y;
    const int t0 = blockIdx.x * TG;
    const int tid = threadIdx.x;

    for (int i = tid; i < H_; i += 512) s_wr[i] = W_rect[i];
    for (int i = tid; i < TG * H_; i += 512) {
        int j = i / H_, h = i % H_;
        s_hid[j][h] = hiddens[(size_t)(b * T_ + t0 + j) * H_ + h];
    }
    __syncthreads();

    const int warp = tid >> 5;
    const int lane = tid & 31;

    for (int p = warp; p < P_; p += 16) {
        const float4* mrow = (const float4*)(mlo + (size_t)(b * P_ + p) * H_);
        float acc[TG] = {};
        #pragma unroll
        for (int q = lane; q < H_ / 4; q += 32) {
            float4 x = mrow[q];
            float4 w = ((const float4*)s_wr)[q];
            #pragma unroll
            for (int j = 0; j < TG; j++) {
                float4 hd = ((const float4*)s_hid[j])[q];
                acc[j] += fmaxf(x.x + hd.x, 0.f) * w.x
                        + fmaxf(x.y + hd.y, 0.f) * w.y
                        + fmaxf(x.z + hd.z, 0.f) * w.z
                        + fmaxf(x.w + hd.w, 0.f) * w.w;
            }
        }
        #pragma unroll
        for (int j = 0; j < TG; j++) {
            float v = acc[j];
            #pragma unroll
            for (int o = 16; o > 0; o >>= 1) v += __shfl_xor_sync(0xffffffffu, v, o);
            if (lane == 0) s_sc[j][p] = v;
        }
    }
    __syncthreads();

    if (warp < TG) {
        const int j = warp;
        float mx = -1e30f;
        for (int p = lane; p < P_; p += 32) mx = fmaxf(mx, s_sc[j][p]);
        #pragma unroll
        for (int o = 16; o > 0; o >>= 1) mx = fmaxf(mx, __shfl_xor_sync(0xffffffffu, mx, o));
        float sm = 0.f;
        for (int p = lane; p < P_; p += 32) {
            float e = expf(s_sc[j][p] - mx);
            s_sc[j][p] = e;
            sm += e;
        }
        #pragma unroll
        for (int o = 16; o > 0; o >>= 1) sm += __shfl_xor_sync(0xffffffffu, sm, o);
        float inv = 1.f / sm;
        float* ap = attn_out + (size_t)(b * T_ + t0 + j) * P_;
        for (int p = lane; p < P_; p += 32) ap[p] = s_sc[j][p] * inv;
    }
}

// ---------------------------------------------------------------------------
// ctx[b,t,m] = sum_p attn[b,t,p] * fm[b,p,m]; writes bf16 hi/lo split.
// 512 threads; 16 warps x 4 t's; 7-deep LDG.128 pipeline.
// ---------------------------------------------------------------------------
__global__ void __launch_bounds__(512)
ctx_kernel(const float* __restrict__ attn, const float* __restrict__ fm,
           __nv_bfloat16* __restrict__ cxh, __nv_bfloat16* __restrict__ cxl)
{
    extern __shared__ float2 s_at2[];     // [64][P_] duplicated pairs (100 KB)
    const int m0 = blockIdx.x * 128;
    const int b  = blockIdx.y;
    const int tid = threadIdx.x;
    const int tx = tid & 31;
    const int ty = tid >> 5;

    for (int i = tid; i < T_ * P_; i += 512) {
        float v = attn[(size_t)b * T_ * P_ + i];
        s_at2[i] = make_float2(v, v);
    }
    __syncthreads();

    unsigned long long acc[4][2] = {};
    const float* fmb = fm + (size_t)b * P_ * MD + m0 + tx * 4;

    for (int p0 = 0; p0 < P_; p0 += 7) {          // 196 = 28 * 7
        unsigned long long f[7][2];
        #pragma unroll
        for (int j = 0; j < 7; j++) {
            float4 v = *(const float4*)(fmb + (size_t)(p0 + j) * MD);
            f[j][0] = *(unsigned long long*)&v.x;
            f[j][1] = *(unsigned long long*)&v.z;
        }
        #pragma unroll
        for (int j = 0; j < 7; j++) {
            #pragma unroll
            for (int i = 0; i < 4; i++) {
                unsigned long long av =
                    *(const unsigned long long*)&s_at2[(ty * 4 + i) * P_ + p0 + j];
                acc[i][0] = ffma2(av, f[j][0], acc[i][0]);
                acc[i][1] = ffma2(av, f[j][1], acc[i][1]);
            }
        }
    }

    #pragma unroll
    for (int i = 0; i < 4; i++) {
        float2 c01 = unpack2(acc[i][0]);
        float2 c23 = unpack2(acc[i][1]);
        float v0 = c01.x, v1 = c01.y, v2 = c23.x, v3 = c23.y;
        __nv_bfloat16 h0 = __float2bfloat16(v0), h1 = __float2bfloat16(v1);
        __nv_bfloat16 h2 = __float2bfloat16(v2), h3 = __float2bfloat16(v3);
        __nv_bfloat16 l0 = __float2bfloat16(v0 - __bfloat162float(h0));
        __nv_bfloat16 l1 = __float2bfloat16(v1 - __bfloat162float(h1));
        __nv_bfloat16 l2 = __float2bfloat16(v2 - __bfloat162float(h2));
        __nv_bfloat16 l3 = __float2bfloat16(v3 - __bfloat162float(h3));
        size_t off = (size_t)(b * T_ + ty * 4 + i) * MD + m0 + tx * 4;
        __nv_bfloat162 ha = __halves2bfloat162(h0, h1), hb = __halves2bfloat162(h2, h3);
        __nv_bfloat162 la = __halves2bfloat162(l0, l1), lb = __halves2bfloat162(l2, l3);
        uint2 uh, ul;
        uh.x = *(uint32_t*)&ha; uh.y = *(uint32_t*)&hb;
        ul.x = *(uint32_t*)&la; ul.y = *(uint32_t*)&lb;
        *(uint2*)(cxh + off) = uh;
        *(uint2*)(cxl + off) = ul;
    }
}

// ---------------------------------------------------------------------------
// launch
// ---------------------------------------------------------------------------
extern "C" void kernel_launch(void* const* d_in, const int* in_sizes, int n_in,
                              void* d_out, int out_size)
{
    const float* maps    = (const float*)d_in[0];
    const float* hiddens = (const float*)d_in[1];
    const float* W_map   = (const float*)d_in[2];
    const float* b_map   = (const float*)d_in[3];
    const float* W_final = (const float*)d_in[4];
    const float* b_final = (const float*)d_in[5];
    const float* W_rect  = (const float*)d_in[6];
    // d_in[7] = b_rect : softmax-invariant, unused.

    float* out = (float*)d_out;       // [out (BT,H) | attn (BT,P)]

    void *v0, *v1, *v2, *v3, *v4, *v5, *v6, *v7, *v8, *v9;
    cudaGetSymbolAddress(&v0, g_mlo);
    cudaGetSymbolAddress(&v1, g_attn_fb);
    cudaGetSymbolAddress(&v2, g_a_hi);  cudaGetSymbolAddress(&v3, g_a_lo);
    cudaGetSymbolAddress(&v4, g_wm_hi); cudaGetSymbolAddress(&v5, g_wm_lo);
    cudaGetSymbolAddress(&v6, g_wf_hi); cudaGetSymbolAddress(&v7, g_wf_lo);
    cudaGetSymbolAddress(&v8, g_cx_hi); cudaGetSymbolAddress(&v9, g_cx_lo);
    float* p_mlo = (float*)v0;
    __nv_bfloat16 *aHi = (__nv_bfloat16*)v2, *aLo = (__nv_bfloat16*)v3;
    __nv_bfloat16 *wmHi = (__nv_bfloat16*)v4, *wmLo = (__nv_bfloat16*)v5;
    __nv_bfloat16 *wfHi = (__nv_bfloat16*)v6, *wfLo = (__nv_bfloat16*)v7;
    __nv_bfloat16 *cxHi = (__nv_bfloat16*)v8, *cxLo = (__nv_bfloat16*)v9;

    float* attn = (out_size >= BT * H_ + BT * P_) ? out + (size_t)BT * H_
                                                  : (float*)v1;

    // GEMM1: MT=2, NWM=2 -> BM=64, BN=64.  GEMM4: MT=1, NWM=4 -> BM=64, BN=32.
    constexpr int SMEM_G1 = 2 * (2 * 64 * 128 + 2 * 64 * 128);   // 65536
    constexpr int SMEM_G4 = 2 * (2 * 64 * 128 + 2 * 32 * 128);   // 49152
    cudaFuncSetAttribute((const void*)gemm_mma_bf16x3<2, 2>,
                         cudaFuncAttributeMaxDynamicSharedMemorySize, SMEM_G1);
    cudaFuncSetAttribute((const void*)gemm_mma_bf16x3<1, 4>,
                         cudaFuncAttributeMaxDynamicSharedMemorySize, SMEM_G4);
    const int ctxSmem = T_ * P_ * (int)sizeof(float2);
    cudaFuncSetAttribute(ctx_kernel,
                         cudaFuncAttributeMaxDynamicSharedMemorySize, ctxSmem);

    // 1. fused split-convert of maps, W_map, W_final to bf16 hi/lo
    convert_split_all<<<1184, 256>>>((const float4*)maps, (const float4*)W_map,
                                     (const float4*)W_final,
                                     (uint2*)aHi, (uint2*)aLo,
                                     (uint2*)wmHi, (uint2*)wmLo,
                                     (uint2*)wfHi, (uint2*)wfLo);

    // 2. mlo = maps @ W_map^T + b_map   (25 x 12 = 300 blocks, 2 CTAs/SM)
    gemm_mma_bf16x3<2, 2><<<dim3((BP + 63) / 64, H_ / 64), 256, SMEM_G1>>>(
        aHi, aLo, wmHi, wmLo, b_map, nullptr, p_mlo, BP);

    // 3. scores + softmax -> attn
    scores_softmax_kernel<<<dim3(T_ / 8, B_), 512>>>(p_mlo, hiddens, W_rect, attn);

    // 4. ctx = attn @ fm  (writes bf16 hi/lo split directly)
    ctx_kernel<<<dim3(MD / 128, B_), 512, ctxSmem>>>(attn, maps, cxHi, cxLo);

    // 5. out = ctx @ W_final^T + b_final + hiddens   (8 x 24 = 192 blocks)
    gemm_mma_bf16x3<1, 4><<<dim3(BT / 64, H_ / 32), 256, SMEM_G4>>>(
        cxHi, cxLo, wfHi, wfLo, b_final, hiddens, out, BT);
}

// round 10
// speedup vs baseline: 3.6099x; 1.9262x over previous
#include <cuda_runtime.h>
#include <cuda_bf16.h>
#include <math.h>
#include <stdint.h>

// Problem constants
constexpr int B_  = 8;
constexpr int P_  = 196;
constexpr int T_  = 64;
constexpr int H_  = 768;
constexpr int MD  = 2048;
constexpr int BP  = B_ * P_;   // 1568
constexpr int BT  = B_ * T_;   // 512
constexpr int NCH = MD / 64;   // 32 K-chunks of 64

// ---------------------------------------------------------------------------
// Scratch (device globals; no allocation allowed)
// ---------------------------------------------------------------------------
__device__ float g_mlo[BP * H_];
__device__ float g_attn_fb[BT * P_];       // raw scores scratch (+ attn fallback)
__device__ __align__(16) __nv_bfloat16 g_a_hi[BP * MD],  g_a_lo[BP * MD];
__device__ __align__(16) __nv_bfloat16 g_wm_hi[H_ * MD], g_wm_lo[H_ * MD];
__device__ __align__(16) __nv_bfloat16 g_wf_hi[H_ * MD], g_wf_lo[H_ * MD];
__device__ __align__(16) __nv_bfloat16 g_cx_hi[BT * MD], g_cx_lo[BT * MD];

// ---------------------------------------------------------------------------
// PTX helpers (base-ISA only: ldmatrix / mma.sync / cp.async)
// ---------------------------------------------------------------------------
__device__ __forceinline__ uint32_t smem_u32(const void* p) {
    uint32_t a;
    asm("{ .reg .u64 t; cvta.to.shared.u64 t, %1; cvt.u32.u64 %0, t; }"
        : "=r"(a) : "l"(p));
    return a;
}
__device__ __forceinline__ uint32_t swz(uint32_t o) { return o ^ ((o >> 3) & 0x70); }

__device__ __forceinline__ void cp16(uint32_t dst, const void* src, int srcsz) {
    asm volatile("cp.async.cg.shared.global [%0], [%1], 16, %2;"
                 :: "r"(dst), "l"(src), "r"(srcsz));
}
__device__ __forceinline__ void ldsm_x4(uint32_t& r0, uint32_t& r1, uint32_t& r2,
                                        uint32_t& r3, uint32_t a) {
    asm volatile("ldmatrix.sync.aligned.m8n8.x4.shared.b16 {%0,%1,%2,%3}, [%4];"
                 : "=r"(r0), "=r"(r1), "=r"(r2), "=r"(r3) : "r"(a));
}
// B operand: W stored [n][k] row-major == column-major B(k,n) -> NO trans.
__device__ __forceinline__ void ldsm_x2(uint32_t& r0, uint32_t& r1, uint32_t a) {
    asm volatile("ldmatrix.sync.aligned.m8n8.x2.shared.b16 {%0,%1}, [%2];"
                 : "=r"(r0), "=r"(r1) : "r"(a));
}
__device__ __forceinline__ void mma16816(float c[4], const uint32_t a[4],
                                         const uint32_t b[2]) {
    asm volatile("mma.sync.aligned.m16n8k16.row.col.f32.bf16.bf16.f32 "
                 "{%0,%1,%2,%3}, {%4,%5,%6,%7}, {%8,%9}, {%0,%1,%2,%3};"
                 : "+f"(c[0]), "+f"(c[1]), "+f"(c[2]), "+f"(c[3])
                 : "r"(a[0]), "r"(a[1]), "r"(a[2]), "r"(a[3]),
                   "r"(b[0]), "r"(b[1]));
}

// f32x2 helpers (ctx kernel)
__device__ __forceinline__ unsigned long long ffma2(unsigned long long a,
                                                    unsigned long long b,
                                                    unsigned long long c) {
    unsigned long long d;
    asm("fma.rn.f32x2 %0, %1, %2, %3;" : "=l"(d) : "l"(a), "l"(b), "l"(c));
    return d;
}
__device__ __forceinline__ float2 unpack2(unsigned long long v) {
    float2 f;
    asm("mov.b64 {%0, %1}, %2;" : "=f"(f.x), "=f"(f.y) : "l"(v));
    return f;
}

// ---------------------------------------------------------------------------
// Fused fp32 -> (bf16 hi, bf16 lo) split conversion for all three tensors.
// ---------------------------------------------------------------------------
constexpr int N4_A = BP * MD / 4;     // 802816
constexpr int N4_W = H_ * MD / 4;     // 393216
constexpr int N4_TOT = N4_A + 2 * N4_W;

__global__ void convert_split_all(const float4* __restrict__ sA,
                                  const float4* __restrict__ sWm,
                                  const float4* __restrict__ sWf,
                                  uint2* __restrict__ aH, uint2* __restrict__ aL,
                                  uint2* __restrict__ wmH, uint2* __restrict__ wmL,
                                  uint2* __restrict__ wfH, uint2* __restrict__ wfL)
{
    for (int i = blockIdx.x * 256 + threadIdx.x; i < N4_TOT; i += gridDim.x * 256) {
        const float4* src;
        uint2 *hi, *lo;
        int j;
        if (i < N4_A)              { src = sA;  hi = aH;  lo = aL;  j = i; }
        else if (i < N4_A + N4_W)  { src = sWm; hi = wmH; lo = wmL; j = i - N4_A; }
        else                       { src = sWf; hi = wfH; lo = wfL; j = i - N4_A - N4_W; }
        float4 v = src[j];
        __nv_bfloat16 h0 = __float2bfloat16(v.x), h1 = __float2bfloat16(v.y);
        __nv_bfloat16 h2 = __float2bfloat16(v.z), h3 = __float2bfloat16(v.w);
        __nv_bfloat16 l0 = __float2bfloat16(v.x - __bfloat162float(h0));
        __nv_bfloat16 l1 = __float2bfloat16(v.y - __bfloat162float(h1));
        __nv_bfloat16 l2 = __float2bfloat16(v.z - __bfloat162float(h2));
        __nv_bfloat16 l3 = __float2bfloat16(v.w - __bfloat162float(h3));
        __nv_bfloat162 ha = __halves2bfloat162(h0, h1), hb = __halves2bfloat162(h2, h3);
        __nv_bfloat162 la = __halves2bfloat162(l0, l1), lb = __halves2bfloat162(l2, l3);
        uint2 uh, ul;
        uh.x = *(uint32_t*)&ha; uh.y = *(uint32_t*)&hb;
        ul.x = *(uint32_t*)&la; ul.y = *(uint32_t*)&lb;
        hi[j] = uh;
        lo[j] = ul;
    }
}

// ---------------------------------------------------------------------------
// mma.sync split-bf16 TN GEMM (unchanged from round 7)
// ---------------------------------------------------------------------------
template<int MT, int NWM>
__global__ void __launch_bounds__(256, 2)
gemm_mma_bf16x3(const __nv_bfloat16* __restrict__ aHi, const __nv_bfloat16* __restrict__ aLo,
                const __nv_bfloat16* __restrict__ wHi, const __nv_bfloat16* __restrict__ wLo,
                const float* __restrict__ bias, const float* __restrict__ addin,
                float* __restrict__ C, int M)
{
    constexpr int NWN = 8 / NWM;
    constexpr int BM  = NWM * MT * 16;
    constexpr int BN  = NWN * 16;
    constexpr int A_B = BM * 128;
    constexpr int W_B = BN * 128;
    constexpr int BUF = 2 * A_B + 2 * W_B;

    extern __shared__ __align__(1024) char smem[];
    const uint32_t sb = smem_u32(smem);
    const int tid = threadIdx.x, lane = tid & 31, wid = tid >> 5;
    const int wm = wid / NWN, wn = wid % NWN;
    const int m0 = blockIdx.x * BM, n0 = blockIdx.y * BN;

    auto stage = [&](int c) {
        const uint32_t base = sb + (c & 1) * BUF;
        const int kt = c * 64;
        #pragma unroll
        for (int l = 0; l < BM * 8 / 256; l++) {
            int idx = tid + l * 256;
            int r = idx >> 3, cc = idx & 7;
            uint32_t so = swz((uint32_t)(r * 128 + cc * 16));
            int row = m0 + r;
            int sz  = (row < M) ? 16 : 0;
            size_t off = (size_t)(sz ? row : 0) * MD + kt + cc * 8;
            cp16(base + so,       aHi + off, sz);
            cp16(base + A_B + so, aLo + off, sz);
        }
        #pragma unroll
        for (int l = 0; l < BN * 8 / 256; l++) {
            int idx = tid + l * 256;
            int r = idx >> 3, cc = idx & 7;
            uint32_t so = swz((uint32_t)(r * 128 + cc * 16));
            size_t off = (size_t)(n0 + r) * MD + kt + cc * 8;
            cp16(base + 2 * A_B + so,       wHi + off, 16);
            cp16(base + 2 * A_B + W_B + so, wLo + off, 16);
        }
        asm volatile("cp.async.commit_group;" ::: "memory");
    };

    float acc[MT][2][4];
    #pragma unroll
    for (int i = 0; i < MT; i++)
        #pragma unroll
        for (int j = 0; j < 2; j++)
            #pragma unroll
            for (int q = 0; q < 4; q++) acc[i][j][q] = 0.f;

    stage(0);
    stage(1);

    for (int c = 0; c < NCH; c++) {
        asm volatile("cp.async.wait_group 1;" ::: "memory");
        __syncthreads();
        const uint32_t base = sb + (c & 1) * BUF;
        const uint32_t Ah = base, Al = base + A_B;
        const uint32_t Wh = base + 2 * A_B, Wl = Wh + W_B;

        #pragma unroll
        for (int ks = 0; ks < 4; ks++) {
            uint32_t bh[2][2], bl[2][2];
            #pragma unroll
            for (int nt = 0; nt < 2; nt++) {
                uint32_t so = swz((uint32_t)((wn * 16 + nt * 8 + (lane & 7)) * 128
                                             + ks * 32 + ((lane >> 3) & 1) * 16));
                ldsm_x2(bh[nt][0], bh[nt][1], Wh + so);
                ldsm_x2(bl[nt][0], bl[nt][1], Wl + so);
            }
            #pragma unroll
            for (int mt = 0; mt < MT; mt++) {
                uint32_t so = swz((uint32_t)((wm * (MT * 16) + mt * 16 + (lane & 15)) * 128
                                             + ks * 32 + (lane >> 4) * 16));
                uint32_t ah[4], al[4];
                ldsm_x4(ah[0], ah[1], ah[2], ah[3], Ah + so);
                ldsm_x4(al[0], al[1], al[2], al[3], Al + so);
                #pragma unroll
                for (int nt = 0; nt < 2; nt++) {
                    mma16816(acc[mt][nt], ah, bh[nt]);
                    mma16816(acc[mt][nt], ah, bl[nt]);
                    mma16816(acc[mt][nt], al, bh[nt]);
                }
            }
        }
        __syncthreads();
        if (c + 2 < NCH) stage(c + 2);
        else asm volatile("cp.async.commit_group;" ::: "memory");
    }
    asm volatile("cp.async.wait_group 0;" ::: "memory");

    #pragma unroll
    for (int mt = 0; mt < MT; mt++) {
        #pragma unroll
        for (int half = 0; half < 2; half++) {
            int row = m0 + wm * (MT * 16) + mt * 16 + half * 8 + (lane >> 2);
            if (row >= M) continue;
            #pragma unroll
            for (int nt = 0; nt < 2; nt++) {
                int col = n0 + wn * 16 + nt * 8 + (lane & 3) * 2;
                float2 v;
                v.x = acc[mt][nt][half * 2 + 0];
                v.y = acc[mt][nt][half * 2 + 1];
                float2 bv = *(const float2*)(bias + col);
                v.x += bv.x; v.y += bv.y;
                if (addin) {
                    float2 h = *(const float2*)(addin + (size_t)row * H_ + col);
                    v.x += h.x; v.y += h.y;
                }
                *(float2*)(C + (size_t)row * H_ + col) = v;
            }
        }
    }
}

// ---------------------------------------------------------------------------
// scores phase 1: raw scores, mlo read exactly once.
// Grid (7 p-tiles, 2 t-halves, 8 b), 256 threads. hiddens tile in smem (96 KB);
// warp holds its 3-4 mlo rows in registers; t-outer loop re-reads only hiddens.
// ---------------------------------------------------------------------------
__global__ void __launch_bounds__(256)
scores_kernel(const float* __restrict__ mlo, const float* __restrict__ hiddens,
              const float* __restrict__ W_rect, float* __restrict__ sc)
{
    extern __shared__ __align__(16) float s_hid[];    // [32][H_] = 96 KB

    const int pt = blockIdx.x;        // 0..6
    const int t0 = blockIdx.y * 32;   // 0 or 32
    const int b  = blockIdx.z;
    const int tid = threadIdx.x, lane = tid & 31, warp = tid >> 5;

    // load hiddens tile (32 x 768 floats)
    {
        const float4* src = (const float4*)(hiddens + (size_t)(b * T_ + t0) * H_);
        float4* dst = (float4*)s_hid;
        for (int i = tid; i < 32 * H_ / 4; i += 256) dst[i] = src[i];
    }

    // W_rect into registers (lane-sliced: h = (q*32+lane)*4 .. +3)
    float4 wr[6];
    #pragma unroll
    for (int q = 0; q < 6; q++) wr[q] = ((const float4*)W_rect)[q * 32 + lane];

    // mlo rows for this warp: p = pt*28 + warp + r*8
    const int nrows = (warp < 4) ? 4 : 3;
    float4 x[4][6];
    #pragma unroll
    for (int r = 0; r < 4; r++) {
        if (r >= nrows) break;
        const int p = pt * 28 + warp + r * 8;
        const float4* mp = (const float4*)(mlo + (size_t)(b * P_ + p) * H_);
        #pragma unroll
        for (int q = 0; q < 6; q++) x[r][q] = mp[q * 32 + lane];
    }
    __syncthreads();

    for (int t = 0; t < 32; t++) {
        float4 hd[6];
        const float4* hp = (const float4*)(s_hid + t * H_);
        #pragma unroll
        for (int q = 0; q < 6; q++) hd[q] = hp[q * 32 + lane];

        float acc[4] = {};
        #pragma unroll
        for (int r = 0; r < 4; r++) {
            if (r >= nrows) break;
            float a = 0.f;
            #pragma unroll
            for (int q = 0; q < 6; q++) {
                a += fmaxf(x[r][q].x + hd[q].x, 0.f) * wr[q].x
                   + fmaxf(x[r][q].y + hd[q].y, 0.f) * wr[q].y
                   + fmaxf(x[r][q].z + hd[q].z, 0.f) * wr[q].z
                   + fmaxf(x[r][q].w + hd[q].w, 0.f) * wr[q].w;
            }
            acc[r] = a;
        }
        #pragma unroll
        for (int r = 0; r < 4; r++) {
            if (r >= nrows) break;
            float v = acc[r];
            #pragma unroll
            for (int o = 16; o > 0; o >>= 1) v += __shfl_xor_sync(0xffffffffu, v, o);
            if (lane == 0)
                sc[(size_t)(b * T_ + t0 + t) * P_ + pt * 28 + warp + r * 8] = v;
        }
    }
}

// ---------------------------------------------------------------------------
// scores phase 2: softmax over p. Warp per (b,t)-row; 64 blocks x 256.
// ---------------------------------------------------------------------------
__global__ void __launch_bounds__(256)
softmax_kernel(const float* __restrict__ sc, float* __restrict__ attn)
{
    const int row = blockIdx.x * 8 + (threadIdx.x >> 5);   // 0..511
    const int lane = threadIdx.x & 31;
    const float* sp = sc + (size_t)row * P_;

    float v[7];
    float mx = -1e30f;
    #pragma unroll
    for (int i = 0; i < 7; i++) {
        int p = lane + i * 32;
        v[i] = (p < P_) ? sp[p] : -1e30f;
        mx = fmaxf(mx, v[i]);
    }
    #pragma unroll
    for (int o = 16; o > 0; o >>= 1) mx = fmaxf(mx, __shfl_xor_sync(0xffffffffu, mx, o));
    float sm = 0.f;
    #pragma unroll
    for (int i = 0; i < 7; i++) {
        v[i] = expf(v[i] - mx);
        sm += v[i];
    }
    #pragma unroll
    for (int o = 16; o > 0; o >>= 1) sm += __shfl_xor_sync(0xffffffffu, sm, o);
    float inv = 1.f / sm;
    float* ap = attn + (size_t)row * P_;
    #pragma unroll
    for (int i = 0; i < 7; i++) {
        int p = lane + i * 32;
        if (p < P_) ap[p] = v[i] * inv;
    }
}

// ---------------------------------------------------------------------------
// ctx v3: ctx[b,t,m] = sum_p attn[b,t,p] * fm[b,p,m]; bf16 hi/lo split output.
// fm staged via cp.async (32-row x 512 B chunks, double-buffered); attn
// transposed+duplicated in smem [p][t]{v,v} (stride 66 float2, pad for STS).
// 512 threads: tx = 32 m-groups, ty = 16 warps x 4 t's.
// ---------------------------------------------------------------------------
constexpr int AT_STRIDE = 66;                        // float2 units per p-row
constexpr int AT_BYTES  = P_ * AT_STRIDE * 8;        // 103,488
constexpr int FM_CHUNK  = 32 * 128 * 4;              // 16 KB
constexpr int CTX_SMEM  = AT_BYTES + 2 * FM_CHUNK;   // 136,256

__global__ void __launch_bounds__(512)
ctx_kernel(const float* __restrict__ attn, const float* __restrict__ fm,
           __nv_bfloat16* __restrict__ cxh, __nv_bfloat16* __restrict__ cxl)
{
    extern __shared__ __align__(16) char smem[];
    float2* s_at2 = (float2*)smem;
    const uint32_t sb = smem_u32(smem);
    const uint32_t fm_base = sb + AT_BYTES;

    const int m0 = blockIdx.x * 128;
    const int b  = blockIdx.y;
    const int tid = threadIdx.x;
    const int tx = tid & 31;
    const int ty = tid >> 5;

    // transpose+duplicate attn into smem (coalesced reads)
    for (int i = tid; i < T_ * P_; i += 512) {
        int t = i / P_, p = i % P_;
        float v = attn[(size_t)(b * T_ + t) * P_ + p];
        s_at2[p * AT_STRIDE + t] = make_float2(v, v);
    }

    const float* fmb = fm + (size_t)b * P_ * MD + m0;
    auto stage = [&](int ch) {
        const int rows = (ch == 6) ? 4 : 32;
        const uint32_t base = fm_base + (ch & 1) * FM_CHUNK;
        for (int i = tid; i < rows * 32; i += 512) {
            int r = i >> 5, c = i & 31;
            cp16(base + r * 512 + c * 16,
                 fmb + (size_t)(ch * 32 + r) * MD + c * 4, 16);
        }
        asm volatile("cp.async.commit_group;" ::: "memory");
    };

    stage(0);
    stage(1);
    __syncthreads();    // also covers s_at2 fill

    unsigned long long acc[4][2] = {};

    for (int ch = 0; ch < 7; ch++) {
        asm volatile("cp.async.wait_group 1;" ::: "memory");
        __syncthreads();
        const float* sf = (const float*)(smem + AT_BYTES + (ch & 1) * FM_CHUNK);
        const int rows = (ch == 6) ? 4 : 32;
        for (int r = 0; r < rows; r++) {
            const int p = ch * 32 + r;
            float4 fv = *(const float4*)(sf + r * 128 + tx * 4);
            unsigned long long f0 = *(unsigned long long*)&fv.x;
            unsigned long long f1 = *(unsigned long long*)&fv.z;
            const float4* ap = (const float4*)(s_at2 + p * AT_STRIDE + ty * 4);
            float4 a01 = ap[0], a23 = ap[1];
            unsigned long long av0 = *(unsigned long long*)&a01.x;
            unsigned long long av1 = *(unsigned long long*)&a01.z;
            unsigned long long av2 = *(unsigned long long*)&a23.x;
            unsigned long long av3 = *(unsigned long long*)&a23.z;
            acc[0][0] = ffma2(av0, f0, acc[0][0]);
            acc[0][1] = ffma2(av0, f1, acc[0][1]);
            acc[1][0] = ffma2(av1, f0, acc[1][0]);
            acc[1][1] = ffma2(av1, f1, acc[1][1]);
            acc[2][0] = ffma2(av2, f0, acc[2][0]);
            acc[2][1] = ffma2(av2, f1, acc[2][1]);
            acc[3][0] = ffma2(av3, f0, acc[3][0]);
            acc[3][1] = ffma2(av3, f1, acc[3][1]);
        }
        __syncthreads();
        if (ch + 2 < 7) stage(ch + 2);
        else asm volatile("cp.async.commit_group;" ::: "memory");
    }
    asm volatile("cp.async.wait_group 0;" ::: "memory");

    #pragma unroll
    for (int i = 0; i < 4; i++) {
        float2 c01 = unpack2(acc[i][0]);
        float2 c23 = unpack2(acc[i][1]);
        float v0 = c01.x, v1 = c01.y, v2 = c23.x, v3 = c23.y;
        __nv_bfloat16 h0 = __float2bfloat16(v0), h1 = __float2bfloat16(v1);
        __nv_bfloat16 h2 = __float2bfloat16(v2), h3 = __float2bfloat16(v3);
        __nv_bfloat16 l0 = __float2bfloat16(v0 - __bfloat162float(h0));
        __nv_bfloat16 l1 = __float2bfloat16(v1 - __bfloat162float(h1));
        __nv_bfloat16 l2 = __float2bfloat16(v2 - __bfloat162float(h2));
        __nv_bfloat16 l3 = __float2bfloat16(v3 - __bfloat162float(h3));
        size_t off = (size_t)(b * T_ + ty * 4 + i) * MD + m0 + tx * 4;
        __nv_bfloat162 ha = __halves2bfloat162(h0, h1), hb = __halves2bfloat162(h2, h3);
        __nv_bfloat162 la = __halves2bfloat162(l0, l1), lb = __halves2bfloat162(l2, l3);
        uint2 uh, ul;
        uh.x = *(uint32_t*)&ha; uh.y = *(uint32_t*)&hb;
        ul.x = *(uint32_t*)&la; ul.y = *(uint32_t*)&lb;
        *(uint2*)(cxh + off) = uh;
        *(uint2*)(cxl + off) = ul;
    }
}

// ---------------------------------------------------------------------------
// launch
// ---------------------------------------------------------------------------
extern "C" void kernel_launch(void* const* d_in, const int* in_sizes, int n_in,
                              void* d_out, int out_size)
{
    const float* maps    = (const float*)d_in[0];
    const float* hiddens = (const float*)d_in[1];
    const float* W_map   = (const float*)d_in[2];
    const float* b_map   = (const float*)d_in[3];
    const float* W_final = (const float*)d_in[4];
    const float* b_final = (const float*)d_in[5];
    const float* W_rect  = (const float*)d_in[6];
    // d_in[7] = b_rect : softmax-invariant, unused.

    float* out = (float*)d_out;       // [out (BT,H) | attn (BT,P)]

    void *v0, *v1, *v2, *v3, *v4, *v5, *v6, *v7, *v8, *v9;
    cudaGetSymbolAddress(&v0, g_mlo);
    cudaGetSymbolAddress(&v1, g_attn_fb);
    cudaGetSymbolAddress(&v2, g_a_hi);  cudaGetSymbolAddress(&v3, g_a_lo);
    cudaGetSymbolAddress(&v4, g_wm_hi); cudaGetSymbolAddress(&v5, g_wm_lo);
    cudaGetSymbolAddress(&v6, g_wf_hi); cudaGetSymbolAddress(&v7, g_wf_lo);
    cudaGetSymbolAddress(&v8, g_cx_hi); cudaGetSymbolAddress(&v9, g_cx_lo);
    float* p_mlo = (float*)v0;
    float* p_sc  = (float*)v1;
    __nv_bfloat16 *aHi = (__nv_bfloat16*)v2, *aLo = (__nv_bfloat16*)v3;
    __nv_bfloat16 *wmHi = (__nv_bfloat16*)v4, *wmLo = (__nv_bfloat16*)v5;
    __nv_bfloat16 *wfHi = (__nv_bfloat16*)v6, *wfLo = (__nv_bfloat16*)v7;
    __nv_bfloat16 *cxHi = (__nv_bfloat16*)v8, *cxLo = (__nv_bfloat16*)v9;

    float* attn = (out_size >= BT * H_ + BT * P_) ? out + (size_t)BT * H_
                                                  : p_sc;     // in-place ok (row-wise)

    constexpr int SMEM_G1 = 2 * (2 * 64 * 128 + 2 * 64 * 128);   // 65536
    constexpr int SMEM_G4 = 2 * (2 * 64 * 128 + 2 * 32 * 128);   // 49152
    constexpr int SMEM_SC = 32 * H_ * 4;                         // 98304
    cudaFuncSetAttribute((const void*)gemm_mma_bf16x3<2, 2>,
                         cudaFuncAttributeMaxDynamicSharedMemorySize, SMEM_G1);
    cudaFuncSetAttribute((const void*)gemm_mma_bf16x3<1, 4>,
                         cudaFuncAttributeMaxDynamicSharedMemorySize, SMEM_G4);
    cudaFuncSetAttribute(scores_kernel,
                         cudaFuncAttributeMaxDynamicSharedMemorySize, SMEM_SC);
    cudaFuncSetAttribute(ctx_kernel,
                         cudaFuncAttributeMaxDynamicSharedMemorySize, CTX_SMEM);

    // 1. fused split-convert of maps, W_map, W_final to bf16 hi/lo
    convert_split_all<<<1184, 256>>>((const float4*)maps, (const float4*)W_map,
                                     (const float4*)W_final,
                                     (uint2*)aHi, (uint2*)aLo,
                                     (uint2*)wmHi, (uint2*)wmLo,
                                     (uint2*)wfHi, (uint2*)wfLo);

    // 2. mlo = maps @ W_map^T + b_map   (25 x 12 = 300 blocks)
    gemm_mma_bf16x3<2, 2><<<dim3((BP + 63) / 64, H_ / 64), 256, SMEM_G1>>>(
        aHi, aLo, wmHi, wmLo, b_map, nullptr, p_mlo, BP);

    // 3a. raw scores (112 blocks)
    scores_kernel<<<dim3(7, 2, B_), 256, SMEM_SC>>>(p_mlo, hiddens, W_rect, p_sc);

    // 3b. softmax over p -> attn (64 blocks)
    softmax_kernel<<<BT / 8, 256>>>(p_sc, attn);

    // 4. ctx = attn @ fm  (128 blocks, writes bf16 hi/lo split)
    ctx_kernel<<<dim3(MD / 128, B_), 512, CTX_SMEM>>>(attn, maps, cxHi, cxLo);

    // 5. out = ctx @ W_final^T + b_final + hiddens   (8 x 24 = 192 blocks)
    gemm_mma_bf16x3<1, 4><<<dim3(BT / 64, H_ / 32), 256, SMEM_G4>>>(
        cxHi, cxLo, wfHi, wfLo, b_final, hiddens, out, BT);
}

// round 11
// speedup vs baseline: 3.6719x; 1.0172x over previous
#include <cuda_runtime.h>
#include <cuda_bf16.h>
#include <math.h>
#include <stdint.h>

// Problem constants
constexpr int B_  = 8;
constexpr int P_  = 196;
constexpr int T_  = 64;
constexpr int H_  = 768;
constexpr int MD  = 2048;
constexpr int BP  = B_ * P_;   // 1568
constexpr int BT  = B_ * T_;   // 512
constexpr int NCH = MD / 64;   // 32 K-chunks of 64

// ---------------------------------------------------------------------------
// Scratch (device globals; no allocation allowed)
// ---------------------------------------------------------------------------
__device__ float g_mlo[BP * H_];
__device__ float g_sc[BT * P_];            // raw scores scratch
__device__ __align__(16) __nv_bfloat16 g_a_hi[BP * MD],  g_a_lo[BP * MD];
__device__ __align__(16) __nv_bfloat16 g_wm_hi[H_ * MD], g_wm_lo[H_ * MD];
__device__ __align__(16) __nv_bfloat16 g_wf_hi[H_ * MD], g_wf_lo[H_ * MD];
__device__ __align__(16) __nv_bfloat16 g_cx_hi[BT * MD], g_cx_lo[BT * MD];

// ---------------------------------------------------------------------------
// PTX helpers (base-ISA only: ldmatrix / mma.sync / cp.async)
// ---------------------------------------------------------------------------
__device__ __forceinline__ uint32_t smem_u32(const void* p) {
    uint32_t a;
    asm("{ .reg .u64 t; cvta.to.shared.u64 t, %1; cvt.u32.u64 %0, t; }"
        : "=r"(a) : "l"(p));
    return a;
}
__device__ __forceinline__ uint32_t swz(uint32_t o) { return o ^ ((o >> 3) & 0x70); }

__device__ __forceinline__ void cp16(uint32_t dst, const void* src, int srcsz) {
    asm volatile("cp.async.cg.shared.global [%0], [%1], 16, %2;"
                 :: "r"(dst), "l"(src), "r"(srcsz));
}
__device__ __forceinline__ void ldsm_x4(uint32_t& r0, uint32_t& r1, uint32_t& r2,
                                        uint32_t& r3, uint32_t a) {
    asm volatile("ldmatrix.sync.aligned.m8n8.x4.shared.b16 {%0,%1,%2,%3}, [%4];"
                 : "=r"(r0), "=r"(r1), "=r"(r2), "=r"(r3) : "r"(a));
}
__device__ __forceinline__ void mma16816(float c[4], const uint32_t a[4],
                                         const uint32_t b[2]) {
    asm volatile("mma.sync.aligned.m16n8k16.row.col.f32.bf16.bf16.f32 "
                 "{%0,%1,%2,%3}, {%4,%5,%6,%7}, {%8,%9}, {%0,%1,%2,%3};"
                 : "+f"(c[0]), "+f"(c[1]), "+f"(c[2]), "+f"(c[3])
                 : "r"(a[0]), "r"(a[1]), "r"(a[2]), "r"(a[3]),
                   "r"(b[0]), "r"(b[1]));
}

// f32x2 helpers (ctx kernel)
__device__ __forceinline__ unsigned long long ffma2(unsigned long long a,
                                                    unsigned long long b,
                                                    unsigned long long c) {
    unsigned long long d;
    asm("fma.rn.f32x2 %0, %1, %2, %3;" : "=l"(d) : "l"(a), "l"(b), "l"(c));
    return d;
}
__device__ __forceinline__ float2 unpack2(unsigned long long v) {
    float2 f;
    asm("mov.b64 {%0, %1}, %2;" : "=f"(f.x), "=f"(f.y) : "l"(v));
    return f;
}

// ---------------------------------------------------------------------------
// Fused fp32 -> (bf16 hi, bf16 lo) split conversion for all three tensors.
// ---------------------------------------------------------------------------
constexpr int N4_A = BP * MD / 4;     // 802816
constexpr int N4_W = H_ * MD / 4;     // 393216
constexpr int N4_TOT = N4_A + 2 * N4_W;

__global__ void convert_split_all(const float4* __restrict__ sA,
                                  const float4* __restrict__ sWm,
                                  const float4* __restrict__ sWf,
                                  uint2* __restrict__ aH, uint2* __restrict__ aL,
                                  uint2* __restrict__ wmH, uint2* __restrict__ wmL,
                                  uint2* __restrict__ wfH, uint2* __restrict__ wfL)
{
    for (int i = blockIdx.x * 256 + threadIdx.x; i < N4_TOT; i += gridDim.x * 256) {
        const float4* src;
        uint2 *hi, *lo;
        int j;
        if (i < N4_A)              { src = sA;  hi = aH;  lo = aL;  j = i; }
        else if (i < N4_A + N4_W)  { src = sWm; hi = wmH; lo = wmL; j = i - N4_A; }
        else                       { src = sWf; hi = wfH; lo = wfL; j = i - N4_A - N4_W; }
        float4 v = src[j];
        __nv_bfloat16 h0 = __float2bfloat16(v.x), h1 = __float2bfloat16(v.y);
        __nv_bfloat16 h2 = __float2bfloat16(v.z), h3 = __float2bfloat16(v.w);
        __nv_bfloat16 l0 = __float2bfloat16(v.x - __bfloat162float(h0));
        __nv_bfloat16 l1 = __float2bfloat16(v.y - __bfloat162float(h1));
        __nv_bfloat16 l2 = __float2bfloat16(v.z - __bfloat162float(h2));
        __nv_bfloat16 l3 = __float2bfloat16(v.w - __bfloat162float(h3));
        __nv_bfloat162 ha = __halves2bfloat162(h0, h1), hb = __halves2bfloat162(h2, h3);
        __nv_bfloat162 la = __halves2bfloat162(l0, l1), lb = __halves2bfloat162(l2, l3);
        uint2 uh, ul;
        uh.x = *(uint32_t*)&ha; uh.y = *(uint32_t*)&hb;
        ul.x = *(uint32_t*)&la; ul.y = *(uint32_t*)&lb;
        hi[j] = uh;
        lo[j] = ul;
    }
}

// ---------------------------------------------------------------------------
// mma.sync split-bf16 TN GEMM. 8 warps NWM x (8/NWM); BM=NWM*MT*16, BN=(8/NWM)*16.
// 3 CTAs/SM target. B fragments via single ldmatrix.x4 (both n-tiles + k-halves).
// ---------------------------------------------------------------------------
template<int MT, int NWM>
__global__ void __launch_bounds__(256, 3)
gemm_mma_bf16x3(const __nv_bfloat16* __restrict__ aHi, const __nv_bfloat16* __restrict__ aLo,
                const __nv_bfloat16* __restrict__ wHi, const __nv_bfloat16* __restrict__ wLo,
                const float* __restrict__ bias, const float* __restrict__ addin,
                float* __restrict__ C, int M)
{
    constexpr int NWN = 8 / NWM;
    constexpr int BM  = NWM * MT * 16;
    constexpr int BN  = NWN * 16;
    constexpr int A_B = BM * 128;
    constexpr int W_B = BN * 128;
    constexpr int BUF = 2 * A_B + 2 * W_B;

    extern __shared__ __align__(1024) char smem[];
    const uint32_t sb = smem_u32(smem);
    const int tid = threadIdx.x, lane = tid & 31, wid = tid >> 5;
    const int wm = wid / NWN, wn = wid % NWN;
    const int m0 = blockIdx.x * BM, n0 = blockIdx.y * BN;

    auto stage = [&](int c) {
        const uint32_t base = sb + (c & 1) * BUF;
        const int kt = c * 64;
        #pragma unroll
        for (int l = 0; l < BM * 8 / 256; l++) {
            int idx = tid + l * 256;
            int r = idx >> 3, cc = idx & 7;
            uint32_t so = swz((uint32_t)(r * 128 + cc * 16));
            int row = m0 + r;
            int sz  = (row < M) ? 16 : 0;
            size_t off = (size_t)(sz ? row : 0) * MD + kt + cc * 8;
            cp16(base + so,       aHi + off, sz);
            cp16(base + A_B + so, aLo + off, sz);
        }
        #pragma unroll
        for (int l = 0; l < BN * 8 / 256; l++) {
            int idx = tid + l * 256;
            int r = idx >> 3, cc = idx & 7;
            uint32_t so = swz((uint32_t)(r * 128 + cc * 16));
            size_t off = (size_t)(n0 + r) * MD + kt + cc * 8;
            cp16(base + 2 * A_B + so,       wHi + off, 16);
            cp16(base + 2 * A_B + W_B + so, wLo + off, 16);
        }
        asm volatile("cp.async.commit_group;" ::: "memory");
    };

    float acc[MT][2][4];
    #pragma unroll
    for (int i = 0; i < MT; i++)
        #pragma unroll
        for (int j = 0; j < 2; j++)
            #pragma unroll
            for (int q = 0; q < 4; q++) acc[i][j][q] = 0.f;

    stage(0);
    stage(1);

    for (int c = 0; c < NCH; c++) {
        asm volatile("cp.async.wait_group 1;" ::: "memory");
        __syncthreads();
        const uint32_t base = sb + (c & 1) * BUF;
        const uint32_t Ah = base, Al = base + A_B;
        const uint32_t Wh = base + 2 * A_B, Wl = Wh + W_B;

        #pragma unroll
        for (int ks = 0; ks < 4; ks++) {
            // B fragments: one ldmatrix.x4 covers both n-tiles x both k-halves.
            // lanes 0-7:(nt0,k0) 8-15:(nt0,k1) 16-23:(nt1,k0) 24-31:(nt1,k1)
            uint32_t bh[2][2], bl[2][2];
            {
                uint32_t so = swz((uint32_t)((wn * 16 + ((lane >> 4) & 1) * 8 + (lane & 7)) * 128
                                             + ks * 32 + ((lane >> 3) & 1) * 16));
                ldsm_x4(bh[0][0], bh[0][1], bh[1][0], bh[1][1], Wh + so);
                ldsm_x4(bl[0][0], bl[0][1], bl[1][0], bl[1][1], Wl + so);
            }
            #pragma unroll
            for (int mt = 0; mt < MT; mt++) {
                uint32_t so = swz((uint32_t)((wm * (MT * 16) + mt * 16 + (lane & 15)) * 128
                                             + ks * 32 + (lane >> 4) * 16));
                uint32_t ah[4], al[4];
                ldsm_x4(ah[0], ah[1], ah[2], ah[3], Ah + so);
                ldsm_x4(al[0], al[1], al[2], al[3], Al + so);
                #pragma unroll
                for (int nt = 0; nt < 2; nt++) {
                    mma16816(acc[mt][nt], ah, bh[nt]);
                    mma16816(acc[mt][nt], ah, bl[nt]);
                    mma16816(acc[mt][nt], al, bh[nt]);
                }
            }
        }
        __syncthreads();
        if (c + 2 < NCH) stage(c + 2);
        else asm volatile("cp.async.commit_group;" ::: "memory");
    }
    asm volatile("cp.async.wait_group 0;" ::: "memory");

    #pragma unroll
    for (int mt = 0; mt < MT; mt++) {
        #pragma unroll
        for (int half = 0; half < 2; half++) {
            int row = m0 + wm * (MT * 16) + mt * 16 + half * 8 + (lane >> 2);
            if (row >= M) continue;
            #pragma unroll
            for (int nt = 0; nt < 2; nt++) {
                int col = n0 + wn * 16 + nt * 8 + (lane & 3) * 2;
                float2 v;
                v.x = acc[mt][nt][half * 2 + 0];
                v.y = acc[mt][nt][half * 2 + 1];
                float2 bv = *(const float2*)(bias + col);
                v.x += bv.x; v.y += bv.y;
                if (addin) {
                    float2 h = *(const float2*)(addin + (size_t)row * H_ + col);
                    v.x += h.x; v.y += h.y;
                }
                *(float2*)(C + (size_t)row * H_ + col) = v;
            }
        }
    }
}

// ---------------------------------------------------------------------------
// scores phase 1: raw scores, mlo read exactly once. (unchanged)
// ---------------------------------------------------------------------------
__global__ void __launch_bounds__(256)
scores_kernel(const float* __restrict__ mlo, const float* __restrict__ hiddens,
              const float* __restrict__ W_rect, float* __restrict__ sc)
{
    extern __shared__ __align__(16) float s_hid[];    // [32][H_] = 96 KB

    const int pt = blockIdx.x;        // 0..6
    const int t0 = blockIdx.y * 32;   // 0 or 32
    const int b  = blockIdx.z;
    const int tid = threadIdx.x, lane = tid & 31, warp = tid >> 5;

    {
        const float4* src = (const float4*)(hiddens + (size_t)(b * T_ + t0) * H_);
        float4* dst = (float4*)s_hid;
        for (int i = tid; i < 32 * H_ / 4; i += 256) dst[i] = src[i];
    }

    float4 wr[6];
    #pragma unroll
    for (int q = 0; q < 6; q++) wr[q] = ((const float4*)W_rect)[q * 32 + lane];

    const int nrows = (warp < 4) ? 4 : 3;
    float4 x[4][6];
    #pragma unroll
    for (int r = 0; r < 4; r++) {
        if (r >= nrows) break;
        const int p = pt * 28 + warp + r * 8;
        const float4* mp = (const float4*)(mlo + (size_t)(b * P_ + p) * H_);
        #pragma unroll
        for (int q = 0; q < 6; q++) x[r][q] = mp[q * 32 + lane];
    }
    __syncthreads();

    for (int t = 0; t < 32; t++) {
        float4 hd[6];
        const float4* hp = (const float4*)(s_hid + t * H_);
        #pragma unroll
        for (int q = 0; q < 6; q++) hd[q] = hp[q * 32 + lane];

        float acc[4] = {};
        #pragma unroll
        for (int r = 0; r < 4; r++) {
            if (r >= nrows) break;
            float a = 0.f;
            #pragma unroll
            for (int q = 0; q < 6; q++) {
                a += fmaxf(x[r][q].x + hd[q].x, 0.f) * wr[q].x
                   + fmaxf(x[r][q].y + hd[q].y, 0.f) * wr[q].y
                   + fmaxf(x[r][q].z + hd[q].z, 0.f) * wr[q].z
                   + fmaxf(x[r][q].w + hd[q].w, 0.f) * wr[q].w;
            }
            acc[r] = a;
        }
        #pragma unroll
        for (int r = 0; r < 4; r++) {
            if (r >= nrows) break;
            float v = acc[r];
            #pragma unroll
            for (int o = 16; o > 0; o >>= 1) v += __shfl_xor_sync(0xffffffffu, v, o);
            if (lane == 0)
                sc[(size_t)(b * T_ + t0 + t) * P_ + pt * 28 + warp + r * 8] = v;
        }
    }
}

// ---------------------------------------------------------------------------
// ctx + fused softmax:
//   attn[b,t,:] = softmax_p(sc[b,t,:]);  ctx[b,t,m] = sum_p attn * fm[b,p,m]
// fm via cp.async double-buffered chunks (issued BEFORE softmax to overlap).
// attn kept in smem transposed+duplicated [p][t]{v,v}. blockIdx.x==0 writes
// the attn output tensor. bf16 hi/lo split epilogue feeds GEMM4.
// ---------------------------------------------------------------------------
constexpr int AT_STRIDE = 66;                        // float2 units per p-row
constexpr int AT_BYTES  = P_ * AT_STRIDE * 8;        // 103,488
constexpr int FM_CHUNK  = 32 * 128 * 4;              // 16 KB
constexpr int CTX_SMEM  = AT_BYTES + 2 * FM_CHUNK;   // 136,256

__global__ void __launch_bounds__(512)
ctx_kernel(const float* __restrict__ sc, const float* __restrict__ fm,
           __nv_bfloat16* __restrict__ cxh, __nv_bfloat16* __restrict__ cxl,
           float* __restrict__ attn_out)
{
    extern __shared__ __align__(16) char smem[];
    float2* s_at2 = (float2*)smem;
    const uint32_t sb = smem_u32(smem);
    const uint32_t fm_base = sb + AT_BYTES;

    const int m0 = blockIdx.x * 128;
    const int b  = blockIdx.y;
    const int tid = threadIdx.x;
    const int tx = tid & 31;            // lane
    const int ty = tid >> 5;            // warp: 4 t's each

    const float* fmb = fm + (size_t)b * P_ * MD + m0;
    auto stage = [&](int ch) {
        const int rows = (ch == 6) ? 4 : 32;
        const uint32_t base = fm_base + (ch & 1) * FM_CHUNK;
        for (int i = tid; i < rows * 32; i += 512) {
            int r = i >> 5, c = i & 31;
            cp16(base + r * 512 + c * 16,
                 fmb + (size_t)(ch * 32 + r) * MD + c * 4, 16);
        }
        asm volatile("cp.async.commit_group;" ::: "memory");
    };

    stage(0);
    stage(1);

    // fused softmax: warp ty handles t = ty*4 .. ty*4+3 (DRAM latency of the
    // cp.async stages is hidden behind this math)
    #pragma unroll
    for (int j = 0; j < 4; j++) {
        const int t = ty * 4 + j;
        const float* sp = sc + (size_t)(b * T_ + t) * P_;
        float v[7];
        float mx = -1e30f;
        #pragma unroll
        for (int i = 0; i < 7; i++) {
            int p = tx + i * 32;
            v[i] = (p < P_) ? sp[p] : -1e30f;
            mx = fmaxf(mx, v[i]);
        }
        #pragma unroll
        for (int o = 16; o > 0; o >>= 1) mx = fmaxf(mx, __shfl_xor_sync(0xffffffffu, mx, o));
        float sm = 0.f;
        #pragma unroll
        for (int i = 0; i < 7; i++) {
            v[i] = expf(v[i] - mx);
            sm += v[i];
        }
        #pragma unroll
        for (int o = 16; o > 0; o >>= 1) sm += __shfl_xor_sync(0xffffffffu, sm, o);
        float inv = 1.f / sm;
        #pragma unroll
        for (int i = 0; i < 7; i++) {
            int p = tx + i * 32;
            if (p < P_) {
                float a = v[i] * inv;
                s_at2[p * AT_STRIDE + t] = make_float2(a, a);
                if (attn_out != nullptr && m0 == 0)
                    attn_out[(size_t)(b * T_ + t) * P_ + p] = a;
            }
        }
    }
    __syncthreads();

    unsigned long long acc[4][2] = {};

    for (int ch = 0; ch < 7; ch++) {
        asm volatile("cp.async.wait_group 1;" ::: "memory");
        __syncthreads();
        const float* sf = (const float*)(smem + AT_BYTES + (ch & 1) * FM_CHUNK);
        const int rows = (ch == 6) ? 4 : 32;
        for (int r = 0; r < rows; r++) {
            const int p = ch * 32 + r;
            float4 fv = *(const float4*)(sf + r * 128 + tx * 4);
            unsigned long long f0 = *(unsigned long long*)&fv.x;
            unsigned long long f1 = *(unsigned long long*)&fv.z;
            const float4* ap = (const float4*)(s_at2 + p * AT_STRIDE + ty * 4);
            float4 a01 = ap[0], a23 = ap[1];
            unsigned long long av0 = *(unsigned long long*)&a01.x;
            unsigned long long av1 = *(unsigned long long*)&a01.z;
            unsigned long long av2 = *(unsigned long long*)&a23.x;
            unsigned long long av3 = *(unsigned long long*)&a23.z;
            acc[0][0] = ffma2(av0, f0, acc[0][0]);
            acc[0][1] = ffma2(av0, f1, acc[0][1]);
            acc[1][0] = ffma2(av1, f0, acc[1][0]);
            acc[1][1] = ffma2(av1, f1, acc[1][1]);
            acc[2][0] = ffma2(av2, f0, acc[2][0]);
            acc[2][1] = ffma2(av2, f1, acc[2][1]);
            acc[3][0] = ffma2(av3, f0, acc[3][0]);
            acc[3][1] = ffma2(av3, f1, acc[3][1]);
        }
        __syncthreads();
        if (ch + 2 < 7) stage(ch + 2);
        else asm volatile("cp.async.commit_group;" ::: "memory");
    }
    asm volatile("cp.async.wait_group 0;" ::: "memory");

    #pragma unroll
    for (int i = 0; i < 4; i++) {
        float2 c01 = unpack2(acc[i][0]);
        float2 c23 = unpack2(acc[i][1]);
        float v0 = c01.x, v1 = c01.y, v2 = c23.x, v3 = c23.y;
        __nv_bfloat16 h0 = __float2bfloat16(v0), h1 = __float2bfloat16(v1);
        __nv_bfloat16 h2 = __float2bfloat16(v2), h3 = __float2bfloat16(v3);
        __nv_bfloat16 l0 = __float2bfloat16(v0 - __bfloat162float(h0));
        __nv_bfloat16 l1 = __float2bfloat16(v1 - __bfloat162float(h1));
        __nv_bfloat16 l2 = __float2bfloat16(v2 - __bfloat162float(h2));
        __nv_bfloat16 l3 = __float2bfloat16(v3 - __bfloat162float(h3));
        size_t off = (size_t)(b * T_ + ty * 4 + i) * MD + m0 + tx * 4;
        __nv_bfloat162 ha = __halves2bfloat162(h0, h1), hb = __halves2bfloat162(h2, h3);
        __nv_bfloat162 la = __halves2bfloat162(l0, l1), lb = __halves2bfloat162(l2, l3);
        uint2 uh, ul;
        uh.x = *(uint32_t*)&ha; uh.y = *(uint32_t*)&hb;
        ul.x = *(uint32_t*)&la; ul.y = *(uint32_t*)&lb;
        *(uint2*)(cxh + off) = uh;
        *(uint2*)(cxl + off) = ul;
    }
}

// ---------------------------------------------------------------------------
// launch
// ---------------------------------------------------------------------------
extern "C" void kernel_launch(void* const* d_in, const int* in_sizes, int n_in,
                              void* d_out, int out_size)
{
    const float* maps    = (const float*)d_in[0];
    const float* hiddens = (const float*)d_in[1];
    const float* W_map   = (const float*)d_in[2];
    const float* b_map   = (const float*)d_in[3];
    const float* W_final = (const float*)d_in[4];
    const float* b_final = (const float*)d_in[5];
    const float* W_rect  = (const float*)d_in[6];
    // d_in[7] = b_rect : softmax-invariant, unused.

    float* out = (float*)d_out;       // [out (BT,H) | attn (BT,P)]

    void *v0, *v1, *v2, *v3, *v4, *v5, *v6, *v7, *v8, *v9;
    cudaGetSymbolAddress(&v0, g_mlo);
    cudaGetSymbolAddress(&v1, g_sc);
    cudaGetSymbolAddress(&v2, g_a_hi);  cudaGetSymbolAddress(&v3, g_a_lo);
    cudaGetSymbolAddress(&v4, g_wm_hi); cudaGetSymbolAddress(&v5, g_wm_lo);
    cudaGetSymbolAddress(&v6, g_wf_hi); cudaGetSymbolAddress(&v7, g_wf_lo);
    cudaGetSymbolAddress(&v8, g_cx_hi); cudaGetSymbolAddress(&v9, g_cx_lo);
    float* p_mlo = (float*)v0;
    float* p_sc  = (float*)v1;
    __nv_bfloat16 *aHi = (__nv_bfloat16*)v2, *aLo = (__nv_bfloat16*)v3;
    __nv_bfloat16 *wmHi = (__nv_bfloat16*)v4, *wmLo = (__nv_bfloat16*)v5;
    __nv_bfloat16 *wfHi = (__nv_bfloat16*)v6, *wfLo = (__nv_bfloat16*)v7;
    __nv_bfloat16 *cxHi = (__nv_bfloat16*)v8, *cxLo = (__nv_bfloat16*)v9;

    float* attn = (out_size >= BT * H_ + BT * P_) ? out + (size_t)BT * H_ : nullptr;

    constexpr int SMEM_G1 = 2 * (2 * 64 * 128 + 2 * 64 * 128);   // 65536
    constexpr int SMEM_G4 = 2 * (2 * 64 * 128 + 2 * 32 * 128);   // 49152
    constexpr int SMEM_SC = 32 * H_ * 4;                         // 98304
    cudaFuncSetAttribute((const void*)gemm_mma_bf16x3<2, 2>,
                         cudaFuncAttributeMaxDynamicSharedMemorySize, SMEM_G1);
    cudaFuncSetAttribute((const void*)gemm_mma_bf16x3<1, 4>,
                         cudaFuncAttributeMaxDynamicSharedMemorySize, SMEM_G4);
    cudaFuncSetAttribute(scores_kernel,
                         cudaFuncAttributeMaxDynamicSharedMemorySize, SMEM_SC);
    cudaFuncSetAttribute(ctx_kernel,
                         cudaFuncAttributeMaxDynamicSharedMemorySize, CTX_SMEM);

    // 1. fused split-convert of maps, W_map, W_final to bf16 hi/lo
    convert_split_all<<<1184, 256>>>((const float4*)maps, (const float4*)W_map,
                                     (const float4*)W_final,
                                     (uint2*)aHi, (uint2*)aLo,
                                     (uint2*)wmHi, (uint2*)wmLo,
                                     (uint2*)wfHi, (uint2*)wfLo);

    // 2. mlo = maps @ W_map^T + b_map   (25 x 12 = 300 blocks, 3 CTAs/SM)
    gemm_mma_bf16x3<2, 2><<<dim3((BP + 63) / 64, H_ / 64), 256, SMEM_G1>>>(
        aHi, aLo, wmHi, wmLo, b_map, nullptr, p_mlo, BP);

    // 3. raw scores (112 blocks)
    scores_kernel<<<dim3(7, 2, B_), 256, SMEM_SC>>>(p_mlo, hiddens, W_rect, p_sc);

    // 4. softmax + ctx fused (128 blocks); block x==0 writes attn output
    ctx_kernel<<<dim3(MD / 128, B_), 512, CTX_SMEM>>>(p_sc, maps, cxHi, cxLo, attn);

    // 5. out = ctx @ W_final^T + b_final + hiddens   (8 x 24 = 192 blocks)
    gemm_mma_bf16x3<1, 4><<<dim3(BT / 64, H_ / 32), 256, SMEM_G4>>>(
        cxHi, cxLo, wfHi, wfLo, b_final, hiddens, out, BT);
}